// round 11
// baseline (speedup 1.0000x reference)
#include <cuda_runtime.h>
#include <math.h>
#include <stdint.h>

#define BB 4
#define NN 32768
#define KK 128
#define MM 1024
#define CC 256
#define GG 32
#define HH 8
#define DD 32

// ---------------- scratch (device globals; no allocation allowed) ----------------
__device__ float g_spec1 [BB*KK*CC];
__device__ float g_spec1m[BB*KK*CC];
__device__ float g_spec2 [BB*KK*CC];
__device__ float g_spec2m[BB*KK*CC];
__device__ float g_xfar  [BB*MM*CC];
__device__ float g_q     [BB*MM*CC];
__device__ float g_kmat  [BB*MM*CC];
__device__ float g_v     [BB*MM*CC];
__device__ float g_ao    [BB*MM*CC];
__device__ float g_proj  [BB*MM*CC];
__device__ float g_gnm   [BB*GG];
__device__ float g_gnr   [BB*GG];

// ---------------- tf32 helpers ----------------
__device__ __forceinline__ float tf32r(float x) {
    uint32_t u; asm("cvt.rna.tf32.f32 %0, %1;" : "=r"(u) : "f"(x));
    return __uint_as_float(u);
}

__device__ __forceinline__ void mma8(float d[4], const uint32_t a[4],
                                     uint32_t b0, uint32_t b1) {
    asm volatile(
        "mma.sync.aligned.m16n8k8.row.col.f32.tf32.tf32.f32 "
        "{%0,%1,%2,%3},{%4,%5,%6,%7},{%8,%9},{%0,%1,%2,%3};\n"
        : "+f"(d[0]), "+f"(d[1]), "+f"(d[2]), "+f"(d[3])
        : "r"(a[0]), "r"(a[1]), "r"(a[2]), "r"(a[3]), "r"(b0), "r"(b1));
}

// ---------------- zero the atomic accumulators ----------------
__global__ void k_zero() {
    int i = blockIdx.x * blockDim.x + threadIdx.x;
    if (i < BB*KK*CC) { g_spec1[i] = 0.f; g_spec2[i] = 0.f; }
}

// =====================================================================
// to_basis via 3x-tf32 mma, raw-fp32 smem, 32-deep K-chunks, dist-1 pipe.
// spec[b,k,c] += sum_n E[b,row(n),k]*mass*X[b,n,c]
// smem: E raw [2][32][136] (layout [n][k]), X raw [2][32][72]
// =====================================================================
#define TOB_SMEM_FLOATS (2*32*136 + 2*32*72)   // 13312 floats = 53248 B

__global__ void __launch_bounds__(256,2) k_tobasis_mma(
    const float* __restrict__ X, const float* __restrict__ mass,
    const float* __restrict__ evecs, const int* __restrict__ gidx,
    float* __restrict__ spec, int chunk, int xRowsPerBatch)
{
    extern __shared__ float sm[];
    float* sE = sm;                 // [2][32][136]
    float* sX = sE + 2*32*136;      // [2][32][72]
#define SE(bf,r,c) sE[(bf)*4352 + (r)*136 + (c)]
#define SX(bf,r,c) sX[(bf)*2304 + (r)*72 + (c)]

    int b  = blockIdx.z;
    int c0 = blockIdx.y * 64;
    int n0 = blockIdx.x * chunk;
    int tid  = threadIdx.x;
    int wid  = tid >> 5, lane = tid & 31;
    int wm   = wid & 3;
    int wn   = wid >> 2;
    int lrow = lane >> 2;
    int lcol = lane & 3;

    int iters = chunk >> 5;

    // fetch mapping: E 32x128 = 1024 float4 (4/thread), X 32x64 = 512 float4 (2/thread)
    int er[4], ec[4];
#pragma unroll
    for (int j = 0; j < 4; j++) { int f = tid + j*256; er[j] = f >> 5; ec[j] = (f & 31) * 4; }
    int xr[2], xc[2];
#pragma unroll
    for (int j = 0; j < 2; j++) { int f = tid + j*256; xr[j] = f >> 4; xc[j] = (f & 15) * 4; }

    float4 fe[4], fx[2]; float fmm[2];

#define TOB_FETCH(it) {                                                        \
        int nb = (it) << 5;                                                    \
        _Pragma("unroll")                                                      \
        for (int j = 0; j < 4; j++) {                                          \
            int n = n0 + nb + er[j];                                           \
            int rr = gidx ? gidx[b*MM + n] : n;                                \
            fe[j] = *reinterpret_cast<const float4*>(&evecs[((size_t)b*NN + rr)*KK + ec[j]]); \
        }                                                                      \
        _Pragma("unroll")                                                      \
        for (int j = 0; j < 2; j++) {                                          \
            int n = n0 + nb + xr[j];                                           \
            int rr = gidx ? gidx[b*MM + n] : n;                                \
            fmm[j] = mass[(size_t)b*NN + rr];                                  \
            fx[j] = *reinterpret_cast<const float4*>(&X[((size_t)b*xRowsPerBatch + n)*CC + c0 + xc[j]]); \
        }                                                                      \
    }

#define TOB_STS(bf) {                                                          \
        _Pragma("unroll")                                                      \
        for (int j = 0; j < 4; j++)                                            \
            *reinterpret_cast<float4*>(&SE(bf, er[j], ec[j])) = fe[j];         \
        _Pragma("unroll")                                                      \
        for (int j = 0; j < 2; j++) {                                          \
            float4 xs = fx[j];                                                 \
            xs.x *= fmm[j]; xs.y *= fmm[j]; xs.z *= fmm[j]; xs.w *= fmm[j];    \
            *reinterpret_cast<float4*>(&SX(bf, xr[j], xc[j])) = xs;            \
        }                                                                      \
    }

    float acc[2][4][4];
#pragma unroll
    for (int mt = 0; mt < 2; mt++)
#pragma unroll
        for (int nt = 0; nt < 4; nt++)
#pragma unroll
            for (int j = 0; j < 4; j++) acc[mt][nt][j] = 0.f;

    TOB_FETCH(0);
    TOB_STS(0);
    __syncthreads();

    for (int i = 0; i < iters; i++) {
        int cur = i & 1;
        if (i + 1 < iters) TOB_FETCH(i + 1);

#pragma unroll
        for (int ks = 0; ks < 4; ks++) {
            int kf = ks*8 + lcol;
            uint32_t Aih[2][4], Ail[2][4];
#pragma unroll
            for (int mt = 0; mt < 2; mt++) {
                int m = wm*32 + mt*16 + lrow;
                float r0 = SE(cur, kf,   m);
                float r1 = SE(cur, kf,   m+8);
                float r2 = SE(cur, kf+4, m);
                float r3 = SE(cur, kf+4, m+8);
                float h0 = tf32r(r0), h1 = tf32r(r1), h2 = tf32r(r2), h3 = tf32r(r3);
                Aih[mt][0] = __float_as_uint(h0);
                Aih[mt][1] = __float_as_uint(h1);
                Aih[mt][2] = __float_as_uint(h2);
                Aih[mt][3] = __float_as_uint(h3);
                Ail[mt][0] = __float_as_uint(r0 - h0);
                Ail[mt][1] = __float_as_uint(r1 - h1);
                Ail[mt][2] = __float_as_uint(r2 - h2);
                Ail[mt][3] = __float_as_uint(r3 - h3);
            }
#pragma unroll
            for (int nt = 0; nt < 4; nt++) {
                int c = wn*32 + nt*8 + lrow;
                float b0r = SX(cur, kf,   c);
                float b1r = SX(cur, kf+4, c);
                float hb0 = tf32r(b0r), hb1 = tf32r(b1r);
                uint32_t bh0 = __float_as_uint(hb0);
                uint32_t bh1 = __float_as_uint(hb1);
                uint32_t bl0 = __float_as_uint(b0r - hb0);
                uint32_t bl1 = __float_as_uint(b1r - hb1);
#pragma unroll
                for (int mt = 0; mt < 2; mt++) {
                    mma8(acc[mt][nt], Aih[mt], bh0, bh1);
                    mma8(acc[mt][nt], Aih[mt], bl0, bl1);
                    mma8(acc[mt][nt], Ail[mt], bh0, bh1);
                }
            }
        }
        if (i + 1 < iters) TOB_STS(cur ^ 1);
        __syncthreads();
    }

#pragma unroll
    for (int mt = 0; mt < 2; mt++) {
#pragma unroll
        for (int nt = 0; nt < 4; nt++) {
            int row0 = wm*32 + mt*16 + lrow;
            int col  = c0 + wn*32 + nt*8 + 2*lcol;
            float* p0 = &spec[((size_t)b*KK + row0    ) * CC + col];
            float* p1 = &spec[((size_t)b*KK + row0 + 8) * CC + col];
            atomicAdd(p0,     acc[mt][nt][0]);
            atomicAdd(p0 + 1, acc[mt][nt][1]);
            atomicAdd(p1,     acc[mt][nt][2]);
            atomicAdd(p1 + 1, acc[mt][nt][3]);
        }
    }
}

// =====================================================================
// generic 3x-tf32 mma GEMM, raw-fp32 smem, 32-deep K-chunks, dist-1 pipe.
// smem: A raw [2][128][36], B raw [2][32][72]
// =====================================================================
#define GEMM_SMEM_FLOATS (2*128*36 + 2*32*72)   // 13824 floats = 55296 B

__global__ void __launch_bounds__(256,2) k_gemm_mma(
    const float* __restrict__ A, const int* __restrict__ gidx, long long aBatch,
    const float* __restrict__ W0, const float* __restrict__ W1,
    const float* __restrict__ W2, long long wBatch,
    const float* __restrict__ bias0, const float* __restrict__ bias1,
    const float* __restrict__ bias2,
    float* __restrict__ out0, float* __restrict__ out1, float* __restrict__ out2,
    long long oBatch, int Kd, int nW)
{
    extern __shared__ float sm[];
    float* sA = sm;                 // [2][128][36]
    float* sB = sA + 2*128*36;      // [2][32][72]
#define SA(bf,r,k) sA[(bf)*4608 + (r)*36 + (k)]
#define SB(bf,r,c) sB[(bf)*2304 + (r)*72 + (c)]

    int z   = blockIdx.z;
    int b   = z / nW;
    int sel = z - b * nW;
    int r0  = blockIdx.x * 128;
    int c0  = blockIdx.y * 64;

    const float* W    = (sel == 0) ? W0    : (sel == 1) ? W1    : W2;
    const float* bias = (sel == 0) ? bias0 : (sel == 1) ? bias1 : bias2;
    float*       out  = (sel == 0) ? out0  : (sel == 1) ? out1  : out2;

    int tid  = threadIdx.x;
    int wid  = tid >> 5, lane = tid & 31;
    int wm   = wid & 3;
    int wn   = wid >> 2;
    int lrow = lane >> 2;
    int lcol = lane & 3;

    const float* Ab = A + (size_t)b * aBatch;
    const float* Wb = W + (size_t)b * wBatch;
    float*       Ob = out + (size_t)b * oBatch;

    int iters = Kd >> 5;

    // fetch mapping: A 128x32 = 1024 float4 (4/thread), B 32x64 = 512 float4 (2/thread)
    int ar[4], ak[4], ga[4];
#pragma unroll
    for (int j = 0; j < 4; j++) {
        int f = tid + j*256;
        ar[j] = f >> 3; ak[j] = (f & 7) * 4;
        ga[j] = gidx ? gidx[b*MM + r0 + ar[j]] : (r0 + ar[j]);
    }
    int br[2], bc[2];
#pragma unroll
    for (int j = 0; j < 2; j++) { int f = tid + j*256; br[j] = f >> 4; bc[j] = (f & 15) * 4; }

    float4 fa[4], fb[2];

#define G_FETCH(it) {                                                          \
        int kc = (it) << 5;                                                    \
        _Pragma("unroll")                                                      \
        for (int j = 0; j < 4; j++)                                            \
            fa[j] = *reinterpret_cast<const float4*>(Ab + (size_t)ga[j] * Kd + kc + ak[j]); \
        _Pragma("unroll")                                                      \
        for (int j = 0; j < 2; j++)                                            \
            fb[j] = *reinterpret_cast<const float4*>(Wb + (size_t)(kc + br[j]) * CC + c0 + bc[j]); \
    }

#define G_STS(bf) {                                                            \
        _Pragma("unroll")                                                      \
        for (int j = 0; j < 4; j++)                                            \
            *reinterpret_cast<float4*>(&SA(bf, ar[j], ak[j])) = fa[j];         \
        _Pragma("unroll")                                                      \
        for (int j = 0; j < 2; j++)                                            \
            *reinterpret_cast<float4*>(&SB(bf, br[j], bc[j])) = fb[j];         \
    }

    float acc[2][4][4];
#pragma unroll
    for (int mt = 0; mt < 2; mt++)
#pragma unroll
        for (int nt = 0; nt < 4; nt++)
#pragma unroll
            for (int j = 0; j < 4; j++) acc[mt][nt][j] = 0.f;

    G_FETCH(0);
    G_STS(0);
    __syncthreads();

    for (int i = 0; i < iters; i++) {
        int cur = i & 1;
        if (i + 1 < iters) G_FETCH(i + 1);

#pragma unroll
        for (int ks = 0; ks < 4; ks++) {
            int kf = ks*8 + lcol;
            uint32_t Aih[2][4], Ail[2][4];
#pragma unroll
            for (int mt = 0; mt < 2; mt++) {
                int m = wm*32 + mt*16 + lrow;
                float r0 = SA(cur, m,   kf);
                float r1 = SA(cur, m+8, kf);
                float r2 = SA(cur, m,   kf+4);
                float r3 = SA(cur, m+8, kf+4);
                float h0 = tf32r(r0), h1 = tf32r(r1), h2 = tf32r(r2), h3 = tf32r(r3);
                Aih[mt][0] = __float_as_uint(h0);
                Aih[mt][1] = __float_as_uint(h1);
                Aih[mt][2] = __float_as_uint(h2);
                Aih[mt][3] = __float_as_uint(h3);
                Ail[mt][0] = __float_as_uint(r0 - h0);
                Ail[mt][1] = __float_as_uint(r1 - h1);
                Ail[mt][2] = __float_as_uint(r2 - h2);
                Ail[mt][3] = __float_as_uint(r3 - h3);
            }
#pragma unroll
            for (int nt = 0; nt < 4; nt++) {
                int c = wn*32 + nt*8 + lrow;
                float b0r = SB(cur, kf,   c);
                float b1r = SB(cur, kf+4, c);
                float hb0 = tf32r(b0r), hb1 = tf32r(b1r);
                uint32_t bh0 = __float_as_uint(hb0);
                uint32_t bh1 = __float_as_uint(hb1);
                uint32_t bl0 = __float_as_uint(b0r - hb0);
                uint32_t bl1 = __float_as_uint(b1r - hb1);
#pragma unroll
                for (int mt = 0; mt < 2; mt++) {
                    mma8(acc[mt][nt], Aih[mt], bh0, bh1);
                    mma8(acc[mt][nt], Aih[mt], bl0, bl1);
                    mma8(acc[mt][nt], Ail[mt], bh0, bh1);
                }
            }
        }
        if (i + 1 < iters) G_STS(cur ^ 1);
        __syncthreads();
    }

#pragma unroll
    for (int mt = 0; mt < 2; mt++) {
#pragma unroll
        for (int nt = 0; nt < 4; nt++) {
            int row0 = r0 + wm*32 + mt*16 + lrow;
            int col  = c0 + wn*32 + nt*8 + 2*lcol;
            float b0v = bias ? bias[col]     : 0.f;
            float b1v = bias ? bias[col + 1] : 0.f;
            float2 v0 = {acc[mt][nt][0] + b0v, acc[mt][nt][1] + b1v};
            float2 v1 = {acc[mt][nt][2] + b0v, acc[mt][nt][3] + b1v};
            *reinterpret_cast<float2*>(&Ob[(size_t)row0       * CC + col]) = v0;
            *reinterpret_cast<float2*>(&Ob[(size_t)(row0 + 8) * CC + col]) = v1;
        }
    }
}

// ---------------- spectral coefficient multiply (+ optional out_w fold) ----------------
__global__ void k_coef(const float* __restrict__ evals, const float* __restrict__ tvec,
                       const float* __restrict__ specin, float* __restrict__ specout,
                       const float* __restrict__ outw)
{
    int bk = blockIdx.x;
    int b = bk >> 7, k = bk & 127;
    int c = threadIdx.x;
    float t = fmaxf(tvec[c], 1e-8f);
    float w = outw ? fmaxf(outw[c], 1e-8f) : 1.f;
    specout[(size_t)bk*CC + c] = expf(-evals[b*KK + k] * t) * specin[(size_t)bk*CC + c] * w;
}

// ---------------- GroupNorm stats ----------------
__global__ void k_gnstats()
{
    int b = blockIdx.x >> 5, g = blockIdx.x & 31;
    int tid = threadIdx.x;
    float s = 0.f, s2 = 0.f;
    for (int e = tid; e < MM*8; e += 256) {
        int m = e >> 3, j = e & 7;
        float v = g_xfar[((size_t)(b*MM + m)) * CC + (g << 3) + j];
        s += v; s2 += v * v;
    }
    __shared__ float rs[256], rq[256];
    rs[tid] = s; rq[tid] = s2;
    __syncthreads();
    for (int o = 128; o > 0; o >>= 1) {
        if (tid < o) { rs[tid] += rs[tid+o]; rq[tid] += rq[tid+o]; }
        __syncthreads();
    }
    if (tid == 0) {
        float mean = rs[0] * (1.f/8192.f);
        float var  = rq[0] * (1.f/8192.f) - mean*mean;
        g_gnm[blockIdx.x] = mean;
        g_gnr[blockIdx.x] = rsqrtf(var + 1e-6f);
    }
}

// ---------------- GroupNorm apply (in place) ----------------
__global__ void k_gnapply(const float* __restrict__ gn_w, const float* __restrict__ gn_b)
{
    int i = blockIdx.x * blockDim.x + threadIdx.x;
    int base = i * 4;
    int c  = base & 255;
    int bm = base >> 8;
    int b  = bm >> 10;
    int g  = c >> 3;
    float mean = g_gnm[b*GG + g];
    float r    = g_gnr[b*GG + g];
    float4 v = *reinterpret_cast<float4*>(&g_xfar[base]);
    v.x = (v.x - mean) * r * gn_w[c+0] + gn_b[c+0];
    v.y = (v.y - mean) * r * gn_w[c+1] + gn_b[c+1];
    v.z = (v.z - mean) * r * gn_w[c+2] + gn_b[c+2];
    v.w = (v.w - mean) * r * gn_w[c+3] + gn_b[c+3];
    *reinterpret_cast<float4*>(&g_xfar[base]) = v;
}

// =====================================================================
// flash attention with 3x-tf32 mma, raw-fp32 smem + register hi/lo split.
// (unchanged from round 10 — protected win)
// =====================================================================
#define ATT_KP 69
#define ATT_VP 40
#define ATT_PP 68
#define ATT_QP 36
#define ATT_SMEM_FLOATS (32*ATT_KP + 64*ATT_VP + 64*ATT_PP + 256)   // 9376 floats

__global__ void __launch_bounds__(256,2) k_attn_mma()
{
    extern __shared__ float sm[];
    float* sK  = sm;                        // [32][69] raw, transposed [d][key]
    float* sV  = sK + 32*ATT_KP;            // [64][40] raw
    float* sP  = sV + 64*ATT_VP;            // [64][68] raw (Q staging [64][36])
    float* sRm = sP + 64*ATT_PP;            // [2][64]
    float* sRl = sRm + 128;                 // [2][64]

    int b = blockIdx.z, h = blockIdx.y, q0 = blockIdx.x * 64;
    int tid = threadIdx.x;
    int wid = tid >> 5, lane = tid & 31;
    int wm = wid & 3, wn = wid >> 2;
    int lrow = lane >> 2, lcol = lane & 3;
    const float scale = 0.17677669529663687f;   // 1/sqrt(32)
    const float L2E = 1.4426950408889634f;

#pragma unroll
    for (int v = tid; v < 512; v += 256) {
        int r = v >> 3, d0 = (v & 7) * 4;
        float4 qv = *reinterpret_cast<const float4*>(
            &g_q[((size_t)(b*MM) + q0 + r) * CC + h*DD + d0]);
        qv.x *= scale; qv.y *= scale; qv.z *= scale; qv.w *= scale;
        *reinterpret_cast<float4*>(&sP[r*ATT_QP + d0]) = qv;
    }
    __syncthreads();

    uint32_t Aqh[4][4], Aql[4][4];
    {
        int m = 16*wm + lrow;
#pragma unroll
        for (int ks = 0; ks < 4; ks++) {
            int kf = ks*8 + lcol;
            float r0 = sP[m*ATT_QP + kf];
            float r1 = sP[(m+8)*ATT_QP + kf];
            float r2 = sP[m*ATT_QP + kf + 4];
            float r3 = sP[(m+8)*ATT_QP + kf + 4];
            float h0 = tf32r(r0), h1 = tf32r(r1), h2 = tf32r(r2), h3 = tf32r(r3);
            Aqh[ks][0] = __float_as_uint(h0);
            Aqh[ks][1] = __float_as_uint(h1);
            Aqh[ks][2] = __float_as_uint(h2);
            Aqh[ks][3] = __float_as_uint(h3);
            Aql[ks][0] = __float_as_uint(r0 - h0);
            Aql[ks][1] = __float_as_uint(r1 - h1);
            Aql[ks][2] = __float_as_uint(r2 - h2);
            Aql[ks][3] = __float_as_uint(r3 - h3);
        }
    }

    float oacc[2][4];
#pragma unroll
    for (int nt = 0; nt < 2; nt++)
#pragma unroll
        for (int j = 0; j < 4; j++) oacc[nt][j] = 0.f;
    float mrun0 = -1e30f, mrun1 = -1e30f, lrun0 = 0.f, lrun1 = 0.f;
    int rbase = 16*wm + lrow;

    for (int kt = 0; kt < 16; kt++) {
        __syncthreads();
#pragma unroll
        for (int v = tid; v < 512; v += 256) {
            int r = v >> 3, d0 = (v & 7) * 4;
            size_t gi = ((size_t)b*MM + kt*64 + r) * CC + h*DD + d0;
            float4 kv = *reinterpret_cast<const float4*>(&g_kmat[gi]);
            sK[(d0+0)*ATT_KP + r] = kv.x;
            sK[(d0+1)*ATT_KP + r] = kv.y;
            sK[(d0+2)*ATT_KP + r] = kv.z;
            sK[(d0+3)*ATT_KP + r] = kv.w;
            float4 vv = *reinterpret_cast<const float4*>(&g_v[gi]);
            *reinterpret_cast<float4*>(&sV[r*ATT_VP + d0]) = vv;
        }
        __syncthreads();

        float s[4][4];
#pragma unroll
        for (int nt = 0; nt < 4; nt++)
#pragma unroll
            for (int j = 0; j < 4; j++) s[nt][j] = 0.f;
#pragma unroll
        for (int ks = 0; ks < 4; ks++) {
            int kf = ks*8 + lcol;
#pragma unroll
            for (int nt = 0; nt < 4; nt++) {
                int key = wn*32 + nt*8 + lrow;
                float b0r = sK[kf*ATT_KP + key];
                float b1r = sK[(kf+4)*ATT_KP + key];
                float hb0 = tf32r(b0r), hb1 = tf32r(b1r);
                uint32_t bh0 = __float_as_uint(hb0);
                uint32_t bh1 = __float_as_uint(hb1);
                uint32_t bl0 = __float_as_uint(b0r - hb0);
                uint32_t bl1 = __float_as_uint(b1r - hb1);
                mma8(s[nt], Aqh[ks], bh0, bh1);
                mma8(s[nt], Aqh[ks], bl0, bl1);
                mma8(s[nt], Aql[ks], bh0, bh1);
            }
        }

        float t0 = -1e30f, t1 = -1e30f;
#pragma unroll
        for (int nt = 0; nt < 4; nt++) {
            t0 = fmaxf(t0, fmaxf(s[nt][0], s[nt][1]));
            t1 = fmaxf(t1, fmaxf(s[nt][2], s[nt][3]));
        }
        t0 = fmaxf(t0, __shfl_xor_sync(0xffffffff, t0, 1));
        t0 = fmaxf(t0, __shfl_xor_sync(0xffffffff, t0, 2));
        t1 = fmaxf(t1, __shfl_xor_sync(0xffffffff, t1, 1));
        t1 = fmaxf(t1, __shfl_xor_sync(0xffffffff, t1, 2));
        if (lcol == 0) {
            sRm[wn*64 + rbase]     = t0;
            sRm[wn*64 + rbase + 8] = t1;
        }
        __syncthreads();
        float mnew0 = fmaxf(mrun0, fmaxf(sRm[rbase],     sRm[64 + rbase]));
        float mnew1 = fmaxf(mrun1, fmaxf(sRm[rbase + 8], sRm[64 + rbase + 8]));

        float ls0 = 0.f, ls1 = 0.f;
#pragma unroll
        for (int nt = 0; nt < 4; nt++) {
            float p0 = exp2f((s[nt][0] - mnew0) * L2E);
            float p1 = exp2f((s[nt][1] - mnew0) * L2E);
            float p2 = exp2f((s[nt][2] - mnew1) * L2E);
            float p3 = exp2f((s[nt][3] - mnew1) * L2E);
            ls0 += p0 + p1;
            ls1 += p2 + p3;
            int col = wn*32 + nt*8 + 2*lcol;
            float2 w0 = {p0, p1}, w1 = {p2, p3};
            *reinterpret_cast<float2*>(&sP[rbase*ATT_PP + col])     = w0;
            *reinterpret_cast<float2*>(&sP[(rbase+8)*ATT_PP + col]) = w1;
        }
        ls0 += __shfl_xor_sync(0xffffffff, ls0, 1);
        ls0 += __shfl_xor_sync(0xffffffff, ls0, 2);
        ls1 += __shfl_xor_sync(0xffffffff, ls1, 1);
        ls1 += __shfl_xor_sync(0xffffffff, ls1, 2);
        if (lcol == 0) {
            sRl[wn*64 + rbase]     = ls0;
            sRl[wn*64 + rbase + 8] = ls1;
        }
        __syncthreads();
        float lt0 = sRl[rbase]     + sRl[64 + rbase];
        float lt1 = sRl[rbase + 8] + sRl[64 + rbase + 8];
        float c0 = exp2f((mrun0 - mnew0) * L2E);
        float c1 = exp2f((mrun1 - mnew1) * L2E);
        lrun0 = lrun0 * c0 + lt0;
        lrun1 = lrun1 * c1 + lt1;
        mrun0 = mnew0; mrun1 = mnew1;
#pragma unroll
        for (int nt = 0; nt < 2; nt++) {
            oacc[nt][0] *= c0; oacc[nt][1] *= c0;
            oacc[nt][2] *= c1; oacc[nt][3] *= c1;
        }

#pragma unroll
        for (int ks = 0; ks < 8; ks++) {
            int kf = ks*8 + lcol;
            float r0 = sP[rbase*ATT_PP + kf];
            float r1 = sP[(rbase+8)*ATT_PP + kf];
            float r2 = sP[rbase*ATT_PP + kf + 4];
            float r3 = sP[(rbase+8)*ATT_PP + kf + 4];
            float h0 = tf32r(r0), h1 = tf32r(r1), h2 = tf32r(r2), h3 = tf32r(r3);
            uint32_t Aph[4], Apl[4];
            Aph[0] = __float_as_uint(h0);
            Aph[1] = __float_as_uint(h1);
            Aph[2] = __float_as_uint(h2);
            Aph[3] = __float_as_uint(h3);
            Apl[0] = __float_as_uint(r0 - h0);
            Apl[1] = __float_as_uint(r1 - h1);
            Apl[2] = __float_as_uint(r2 - h2);
            Apl[3] = __float_as_uint(r3 - h3);
#pragma unroll
            for (int nt = 0; nt < 2; nt++) {
                int d = wn*16 + nt*8 + lrow;
                float b0r = sV[kf*ATT_VP + d];
                float b1r = sV[(kf+4)*ATT_VP + d];
                float hb0 = tf32r(b0r), hb1 = tf32r(b1r);
                uint32_t bh0 = __float_as_uint(hb0);
                uint32_t bh1 = __float_as_uint(hb1);
                uint32_t bl0 = __float_as_uint(b0r - hb0);
                uint32_t bl1 = __float_as_uint(b1r - hb1);
                mma8(oacc[nt], Aph, bh0, bh1);
                mma8(oacc[nt], Aph, bl0, bl1);
                mma8(oacc[nt], Apl, bh0, bh1);
            }
        }
    }

    float i0 = 1.f / lrun0, i1 = 1.f / lrun1;
#pragma unroll
    for (int nt = 0; nt < 2; nt++) {
        int col = h*DD + wn*16 + nt*8 + 2*lcol;
        size_t o0 = ((size_t)(b*MM) + q0 + rbase) * CC + col;
        size_t o1 = ((size_t)(b*MM) + q0 + rbase + 8) * CC + col;
        float2 w0 = {oacc[nt][0]*i0, oacc[nt][1]*i0};
        float2 w1 = {oacc[nt][2]*i1, oacc[nt][3]*i1};
        *reinterpret_cast<float2*>(&g_ao[o0]) = w0;
        *reinterpret_cast<float2*>(&g_ao[o1]) = w1;
    }
}

// ---------------- launch ----------------
extern "C" void kernel_launch(void* const* d_in, const int* in_sizes, int n_in,
                              void* d_out, int out_size)
{
    const float* x       = (const float*)d_in[0];
    const float* mass    = (const float*)d_in[1];
    const float* evals   = (const float*)d_in[2];
    const float* evecs   = (const float*)d_in[3];
    const int*   far_idx = (const int*)  d_in[4];
    const float* t_in    = (const float*)d_in[5];
    const float* t_out   = (const float*)d_in[6];
    const float* gn_w    = (const float*)d_in[7];
    const float* gn_b    = (const float*)d_in[8];
    const float* Wq      = (const float*)d_in[9];
    const float* bq      = (const float*)d_in[10];
    const float* Wk      = (const float*)d_in[11];
    const float* bk      = (const float*)d_in[12];
    const float* Wv      = (const float*)d_in[13];
    const float* bv      = (const float*)d_in[14];
    const float* Wo      = (const float*)d_in[15];
    const float* bo      = (const float*)d_in[16];
    const float* out_w   = (const float*)d_in[17];
    float* out = (float*)d_out;

    static int s_attr_done = 0;
    const int TOB_SMEM  = TOB_SMEM_FLOATS  * 4;
    const int GEMM_SMEM = GEMM_SMEM_FLOATS * 4;
    const int ATT_SMEM  = ATT_SMEM_FLOATS  * 4;
    if (!s_attr_done) {
        cudaFuncSetAttribute(k_tobasis_mma, cudaFuncAttributeMaxDynamicSharedMemorySize, TOB_SMEM);
        cudaFuncSetAttribute(k_gemm_mma,    cudaFuncAttributeMaxDynamicSharedMemorySize, GEMM_SMEM);
        cudaFuncSetAttribute(k_attn_mma,    cudaFuncAttributeMaxDynamicSharedMemorySize, ATT_SMEM);
        s_attr_done = 1;
    }

    float *p_spec1, *p_spec1m, *p_spec2, *p_spec2m, *p_xfar, *p_q, *p_k, *p_v, *p_ao, *p_proj;
    cudaGetSymbolAddress((void**)&p_spec1,  g_spec1);
    cudaGetSymbolAddress((void**)&p_spec1m, g_spec1m);
    cudaGetSymbolAddress((void**)&p_spec2,  g_spec2);
    cudaGetSymbolAddress((void**)&p_spec2m, g_spec2m);
    cudaGetSymbolAddress((void**)&p_xfar,   g_xfar);
    cudaGetSymbolAddress((void**)&p_q,      g_q);
    cudaGetSymbolAddress((void**)&p_k,      g_kmat);
    cudaGetSymbolAddress((void**)&p_v,      g_v);
    cudaGetSymbolAddress((void**)&p_ao,     g_ao);
    cudaGetSymbolAddress((void**)&p_proj,   g_proj);

    const long long AKC = (long long)KK * CC;
    const long long AMC = (long long)MM * CC;
    const long long ANK = (long long)NN * KK;
    const long long ANC = (long long)NN * CC;

    k_zero<<<512, 256>>>();

    // to_basis 1: full N, split-K over 32 chunks of 1024
    k_tobasis_mma<<<dim3(32, 4, BB), 256, TOB_SMEM>>>(x, mass, evecs, nullptr, p_spec1, 1024, NN);
    k_coef<<<BB*KK, CC>>>(evals, t_in, p_spec1, p_spec1m, nullptr);

    // from_basis 1: only the M gathered rows
    k_gemm_mma<<<dim3(MM/128, 4, BB), 256, GEMM_SMEM>>>(
        evecs, far_idx, ANK,
        p_spec1m, nullptr, nullptr, AKC,
        nullptr, nullptr, nullptr,
        p_xfar, nullptr, nullptr, AMC, KK, 1);

    // GroupNorm
    k_gnstats<<<BB*GG, 256>>>();
    k_gnapply<<<(BB*MM*CC/4)/256, 256>>>(gn_w, gn_b);

    // QKV projections fused (nW=3)
    k_gemm_mma<<<dim3(MM/128, 4, BB*3), 256, GEMM_SMEM>>>(
        p_xfar, nullptr, AMC,
        Wq, Wk, Wv, 0,
        bq, bk, bv,
        p_q, p_k, p_v, AMC, CC, 3);

    // attention (tensor-core flash, raw smem)
    k_attn_mma<<<dim3(MM/64, HH, BB), 256, ATT_SMEM>>>();

    // output projection
    k_gemm_mma<<<dim3(MM/128, 4, BB), 256, GEMM_SMEM>>>(
        p_ao, nullptr, AMC,
        Wo, nullptr, nullptr, 0,
        bo, nullptr, nullptr,
        p_proj, nullptr, nullptr, AMC, CC, 1);

    // to_basis 2: only the M scattered rows
    k_tobasis_mma<<<dim3(8, 4, BB), 256, TOB_SMEM>>>(p_proj, mass, evecs, far_idx, p_spec2, 128, MM);
    k_coef<<<BB*KK, CC>>>(evals, t_out, p_spec2, p_spec2m, out_w);

    // from_basis 2: full N output (out_w folded into spec2m)
    k_gemm_mma<<<dim3(NN/128, 4, BB), 256, GEMM_SMEM>>>(
        evecs, nullptr, ANK,
        p_spec2m, nullptr, nullptr, AKC,
        nullptr, nullptr, nullptr,
        out, nullptr, nullptr, ANC, KK, 1);
}

// round 14
// speedup vs baseline: 1.0975x; 1.0975x over previous
#include <cuda_runtime.h>
#include <math.h>
#include <stdint.h>

#define BB 4
#define NN 32768
#define KK 128
#define MM 1024
#define CC 256
#define GG 32
#define HH 8
#define DD 32

// ---------------- scratch (device globals; no allocation allowed) ----------------
__device__ float g_spec1 [BB*KK*CC];
__device__ float g_spec1m[BB*KK*CC];
__device__ float g_spec2 [BB*KK*CC];
__device__ float g_spec2m[BB*KK*CC];
__device__ float g_xfar  [BB*MM*CC];
__device__ float g_q     [BB*MM*CC];
__device__ float g_kmat  [BB*MM*CC];
__device__ float g_v     [BB*MM*CC];
__device__ float g_ao    [BB*MM*CC];
__device__ float g_proj  [BB*MM*CC];
__device__ float g_gnm   [BB*GG];
__device__ float g_gnr   [BB*GG];

// ---------------- tf32 helpers ----------------
__device__ __forceinline__ uint32_t tf32u(float x) {
    uint32_t u; asm("cvt.rna.tf32.f32 %0, %1;" : "=r"(u) : "f"(x));
    return u;
}

__device__ __forceinline__ void mma8(float d[4], const uint32_t a[4],
                                     uint32_t b0, uint32_t b1) {
    asm volatile(
        "mma.sync.aligned.m16n8k8.row.col.f32.tf32.tf32.f32 "
        "{%0,%1,%2,%3},{%4,%5,%6,%7},{%8,%9},{%0,%1,%2,%3};\n"
        : "+f"(d[0]), "+f"(d[1]), "+f"(d[2]), "+f"(d[3])
        : "r"(a[0]), "r"(a[1]), "r"(a[2]), "r"(a[3]), "r"(b0), "r"(b1));
}

// ---------------- zero the atomic accumulators ----------------
__global__ void k_zero() {
    int i = blockIdx.x * blockDim.x + threadIdx.x;
    if (i < BB*KK*CC) { g_spec1[i] = 0.f; g_spec2[i] = 0.f; }
}

// =====================================================================
// to_basis via single-pass tf32 mma, raw-fp32 smem, 32-deep K-chunks.
// spec[b,k,c] += sum_n E[b,row(n),k]*mass*X[b,n,c]
// smem: E raw [2][32][136] (layout [n][k]), X raw [2][32][72]
// =====================================================================
#define TOB_SMEM_FLOATS (2*32*136 + 2*32*72)   // 13312 floats = 53248 B

__global__ void __launch_bounds__(256,2) k_tobasis_mma(
    const float* __restrict__ X, const float* __restrict__ mass,
    const float* __restrict__ evecs, const int* __restrict__ gidx,
    float* __restrict__ spec, int chunk, int xRowsPerBatch)
{
    extern __shared__ float sm[];
    float* sE = sm;                 // [2][32][136]
    float* sX = sE + 2*32*136;      // [2][32][72]
#define SE(bf,r,c) sE[(bf)*4352 + (r)*136 + (c)]
#define SX(bf,r,c) sX[(bf)*2304 + (r)*72 + (c)]

    int b  = blockIdx.z;
    int c0 = blockIdx.y * 64;
    int n0 = blockIdx.x * chunk;
    int tid  = threadIdx.x;
    int wid  = tid >> 5, lane = tid & 31;
    int wm   = wid & 3;
    int wn   = wid >> 2;
    int lrow = lane >> 2;
    int lcol = lane & 3;

    int iters = chunk >> 5;

    int er[4], ec[4];
#pragma unroll
    for (int j = 0; j < 4; j++) { int f = tid + j*256; er[j] = f >> 5; ec[j] = (f & 31) * 4; }
    int xr[2], xc[2];
#pragma unroll
    for (int j = 0; j < 2; j++) { int f = tid + j*256; xr[j] = f >> 4; xc[j] = (f & 15) * 4; }

    float4 fe[4], fx[2]; float fmm[2];

#define TOB_FETCH(it) {                                                        \
        int nb = (it) << 5;                                                    \
        _Pragma("unroll")                                                      \
        for (int j = 0; j < 4; j++) {                                          \
            int n = n0 + nb + er[j];                                           \
            int rr = gidx ? gidx[b*MM + n] : n;                                \
            fe[j] = *reinterpret_cast<const float4*>(&evecs[((size_t)b*NN + rr)*KK + ec[j]]); \
        }                                                                      \
        _Pragma("unroll")                                                      \
        for (int j = 0; j < 2; j++) {                                          \
            int n = n0 + nb + xr[j];                                           \
            int rr = gidx ? gidx[b*MM + n] : n;                                \
            fmm[j] = mass[(size_t)b*NN + rr];                                  \
            fx[j] = *reinterpret_cast<const float4*>(&X[((size_t)b*xRowsPerBatch + n)*CC + c0 + xc[j]]); \
        }                                                                      \
    }

#define TOB_STS(bf) {                                                          \
        _Pragma("unroll")                                                      \
        for (int j = 0; j < 4; j++)                                            \
            *reinterpret_cast<float4*>(&SE(bf, er[j], ec[j])) = fe[j];         \
        _Pragma("unroll")                                                      \
        for (int j = 0; j < 2; j++) {                                          \
            float4 xs = fx[j];                                                 \
            xs.x *= fmm[j]; xs.y *= fmm[j]; xs.z *= fmm[j]; xs.w *= fmm[j];    \
            *reinterpret_cast<float4*>(&SX(bf, xr[j], xc[j])) = xs;            \
        }                                                                      \
    }

    float acc[2][4][4];
#pragma unroll
    for (int mt = 0; mt < 2; mt++)
#pragma unroll
        for (int nt = 0; nt < 4; nt++)
#pragma unroll
            for (int j = 0; j < 4; j++) acc[mt][nt][j] = 0.f;

    TOB_FETCH(0);
    TOB_STS(0);
    __syncthreads();

    for (int i = 0; i < iters; i++) {
        int cur = i & 1;
        if (i + 1 < iters) TOB_FETCH(i + 1);

#pragma unroll
        for (int ks = 0; ks < 4; ks++) {
            int kf = ks*8 + lcol;
            uint32_t Af[2][4];
#pragma unroll
            for (int mt = 0; mt < 2; mt++) {
                int m = wm*32 + mt*16 + lrow;
                Af[mt][0] = tf32u(SE(cur, kf,   m));
                Af[mt][1] = tf32u(SE(cur, kf,   m+8));
                Af[mt][2] = tf32u(SE(cur, kf+4, m));
                Af[mt][3] = tf32u(SE(cur, kf+4, m+8));
            }
#pragma unroll
            for (int nt = 0; nt < 4; nt++) {
                int c = wn*32 + nt*8 + lrow;
                uint32_t b0 = tf32u(SX(cur, kf,   c));
                uint32_t b1 = tf32u(SX(cur, kf+4, c));
#pragma unroll
                for (int mt = 0; mt < 2; mt++)
                    mma8(acc[mt][nt], Af[mt], b0, b1);
            }
        }
        if (i + 1 < iters) TOB_STS(cur ^ 1);
        __syncthreads();
    }

#pragma unroll
    for (int mt = 0; mt < 2; mt++) {
#pragma unroll
        for (int nt = 0; nt < 4; nt++) {
            int row0 = wm*32 + mt*16 + lrow;
            int col  = c0 + wn*32 + nt*8 + 2*lcol;
            float* p0 = &spec[((size_t)b*KK + row0    ) * CC + col];
            float* p1 = &spec[((size_t)b*KK + row0 + 8) * CC + col];
            atomicAdd(p0,     acc[mt][nt][0]);
            atomicAdd(p0 + 1, acc[mt][nt][1]);
            atomicAdd(p1,     acc[mt][nt][2]);
            atomicAdd(p1 + 1, acc[mt][nt][3]);
        }
    }
}

// =====================================================================
// generic single-pass tf32 mma GEMM, raw-fp32 smem, 32-deep K-chunks.
// smem: A raw [2][128][36], B raw [2][32][72]
// =====================================================================
#define GEMM_SMEM_FLOATS (2*128*36 + 2*32*72)   // 13824 floats = 55296 B

__global__ void __launch_bounds__(256,2) k_gemm_mma(
    const float* __restrict__ A, const int* __restrict__ gidx, long long aBatch,
    const float* __restrict__ W0, const float* __restrict__ W1,
    const float* __restrict__ W2, long long wBatch,
    const float* __restrict__ bias0, const float* __restrict__ bias1,
    const float* __restrict__ bias2,
    float* __restrict__ out0, float* __restrict__ out1, float* __restrict__ out2,
    long long oBatch, int Kd, int nW)
{
    extern __shared__ float sm[];
    float* sA = sm;                 // [2][128][36]
    float* sB = sA + 2*128*36;      // [2][32][72]
#define SA(bf,r,k) sA[(bf)*4608 + (r)*36 + (k)]
#define SB(bf,r,c) sB[(bf)*2304 + (r)*72 + (c)]

    int z   = blockIdx.z;
    int b   = z / nW;
    int sel = z - b * nW;
    int r0  = blockIdx.x * 128;
    int c0  = blockIdx.y * 64;

    const float* W    = (sel == 0) ? W0    : (sel == 1) ? W1    : W2;
    const float* bias = (sel == 0) ? bias0 : (sel == 1) ? bias1 : bias2;
    float*       out  = (sel == 0) ? out0  : (sel == 1) ? out1  : out2;

    int tid  = threadIdx.x;
    int wid  = tid >> 5, lane = tid & 31;
    int wm   = wid & 3;
    int wn   = wid >> 2;
    int lrow = lane >> 2;
    int lcol = lane & 3;

    const float* Ab = A + (size_t)b * aBatch;
    const float* Wb = W + (size_t)b * wBatch;
    float*       Ob = out + (size_t)b * oBatch;

    int iters = Kd >> 5;

    int ar[4], ak[4], ga[4];
#pragma unroll
    for (int j = 0; j < 4; j++) {
        int f = tid + j*256;
        ar[j] = f >> 3; ak[j] = (f & 7) * 4;
        ga[j] = gidx ? gidx[b*MM + r0 + ar[j]] : (r0 + ar[j]);
    }
    int br[2], bc[2];
#pragma unroll
    for (int j = 0; j < 2; j++) { int f = tid + j*256; br[j] = f >> 4; bc[j] = (f & 15) * 4; }

    float4 fa[4], fb[2];

#define G_FETCH(it) {                                                          \
        int kc = (it) << 5;                                                    \
        _Pragma("unroll")                                                      \
        for (int j = 0; j < 4; j++)                                            \
            fa[j] = *reinterpret_cast<const float4*>(Ab + (size_t)ga[j] * Kd + kc + ak[j]); \
        _Pragma("unroll")                                                      \
        for (int j = 0; j < 2; j++)                                            \
            fb[j] = *reinterpret_cast<const float4*>(Wb + (size_t)(kc + br[j]) * CC + c0 + bc[j]); \
    }

#define G_STS(bf) {                                                            \
        _Pragma("unroll")                                                      \
        for (int j = 0; j < 4; j++)                                            \
            *reinterpret_cast<float4*>(&SA(bf, ar[j], ak[j])) = fa[j];         \
        _Pragma("unroll")                                                      \
        for (int j = 0; j < 2; j++)                                            \
            *reinterpret_cast<float4*>(&SB(bf, br[j], bc[j])) = fb[j];         \
    }

    float acc[2][4][4];
#pragma unroll
    for (int mt = 0; mt < 2; mt++)
#pragma unroll
        for (int nt = 0; nt < 4; nt++)
#pragma unroll
            for (int j = 0; j < 4; j++) acc[mt][nt][j] = 0.f;

    G_FETCH(0);
    G_STS(0);
    __syncthreads();

    for (int i = 0; i < iters; i++) {
        int cur = i & 1;
        if (i + 1 < iters) G_FETCH(i + 1);

#pragma unroll
        for (int ks = 0; ks < 4; ks++) {
            int kf = ks*8 + lcol;
            uint32_t Af[2][4];
#pragma unroll
            for (int mt = 0; mt < 2; mt++) {
                int m = wm*32 + mt*16 + lrow;
                Af[mt][0] = tf32u(SA(cur, m,   kf));
                Af[mt][1] = tf32u(SA(cur, m+8, kf));
                Af[mt][2] = tf32u(SA(cur, m,   kf+4));
                Af[mt][3] = tf32u(SA(cur, m+8, kf+4));
            }
#pragma unroll
            for (int nt = 0; nt < 4; nt++) {
                int c = wn*32 + nt*8 + lrow;
                uint32_t b0 = tf32u(SB(cur, kf,   c));
                uint32_t b1 = tf32u(SB(cur, kf+4, c));
#pragma unroll
                for (int mt = 0; mt < 2; mt++)
                    mma8(acc[mt][nt], Af[mt], b0, b1);
            }
        }
        if (i + 1 < iters) G_STS(cur ^ 1);
        __syncthreads();
    }

#pragma unroll
    for (int mt = 0; mt < 2; mt++) {
#pragma unroll
        for (int nt = 0; nt < 4; nt++) {
            int row0 = r0 + wm*32 + mt*16 + lrow;
            int col  = c0 + wn*32 + nt*8 + 2*lcol;
            float b0v = bias ? bias[col]     : 0.f;
            float b1v = bias ? bias[col + 1] : 0.f;
            float2 v0 = {acc[mt][nt][0] + b0v, acc[mt][nt][1] + b1v};
            float2 v1 = {acc[mt][nt][2] + b0v, acc[mt][nt][3] + b1v};
            *reinterpret_cast<float2*>(&Ob[(size_t)row0       * CC + col]) = v0;
            *reinterpret_cast<float2*>(&Ob[(size_t)(row0 + 8) * CC + col]) = v1;
        }
    }
}

// ---------------- spectral coefficient multiply (+ optional out_w fold) ----------------
__global__ void k_coef(const float* __restrict__ evals, const float* __restrict__ tvec,
                       const float* __restrict__ specin, float* __restrict__ specout,
                       const float* __restrict__ outw)
{
    int bk = blockIdx.x;
    int b = bk >> 7, k = bk & 127;
    int c = threadIdx.x;
    float t = fmaxf(tvec[c], 1e-8f);
    float w = outw ? fmaxf(outw[c], 1e-8f) : 1.f;
    specout[(size_t)bk*CC + c] = expf(-evals[b*KK + k] * t) * specin[(size_t)bk*CC + c] * w;
}

// ---------------- GroupNorm stats ----------------
__global__ void k_gnstats()
{
    int b = blockIdx.x >> 5, g = blockIdx.x & 31;
    int tid = threadIdx.x;
    float s = 0.f, s2 = 0.f;
    for (int e = tid; e < MM*8; e += 256) {
        int m = e >> 3, j = e & 7;
        float v = g_xfar[((size_t)(b*MM + m)) * CC + (g << 3) + j];
        s += v; s2 += v * v;
    }
    __shared__ float rs[256], rq[256];
    rs[tid] = s; rq[tid] = s2;
    __syncthreads();
    for (int o = 128; o > 0; o >>= 1) {
        if (tid < o) { rs[tid] += rs[tid+o]; rq[tid] += rq[tid+o]; }
        __syncthreads();
    }
    if (tid == 0) {
        float mean = rs[0] * (1.f/8192.f);
        float var  = rq[0] * (1.f/8192.f) - mean*mean;
        g_gnm[blockIdx.x] = mean;
        g_gnr[blockIdx.x] = rsqrtf(var + 1e-6f);
    }
}

// ---------------- GroupNorm apply (in place) ----------------
__global__ void k_gnapply(const float* __restrict__ gn_w, const float* __restrict__ gn_b)
{
    int i = blockIdx.x * blockDim.x + threadIdx.x;
    int base = i * 4;
    int c  = base & 255;
    int bm = base >> 8;
    int b  = bm >> 10;
    int g  = c >> 3;
    float mean = g_gnm[b*GG + g];
    float r    = g_gnr[b*GG + g];
    float4 v = *reinterpret_cast<float4*>(&g_xfar[base]);
    v.x = (v.x - mean) * r * gn_w[c+0] + gn_b[c+0];
    v.y = (v.y - mean) * r * gn_w[c+1] + gn_b[c+1];
    v.z = (v.z - mean) * r * gn_w[c+2] + gn_b[c+2];
    v.w = (v.w - mean) * r * gn_w[c+3] + gn_b[c+3];
    *reinterpret_cast<float4*>(&g_xfar[base]) = v;
}

// =====================================================================
// flash attention with single-pass tf32 mma, raw-fp32 smem.
// 64-query tiles, 16 key tiles of 64, online softmax.
// smem (single raw copies): K^T [32][69], V [64][40], P/Q [64][68]
// =====================================================================
#define ATT_KP 69
#define ATT_VP 40
#define ATT_PP 68
#define ATT_QP 36
#define ATT_SMEM_FLOATS (32*ATT_KP + 64*ATT_VP + 64*ATT_PP + 256)   // 9376 floats

__global__ void __launch_bounds__(256,2) k_attn_mma()
{
    extern __shared__ float sm[];
    float* sK  = sm;                        // [32][69] raw, transposed [d][key]
    float* sV  = sK + 32*ATT_KP;            // [64][40] raw
    float* sP  = sV + 64*ATT_VP;            // [64][68] raw (Q staging [64][36])
    float* sRm = sP + 64*ATT_PP;            // [2][64]
    float* sRl = sRm + 128;                 // [2][64]

    int b = blockIdx.z, h = blockIdx.y, q0 = blockIdx.x * 64;
    int tid = threadIdx.x;
    int wid = tid >> 5, lane = tid & 31;
    int wm = wid & 3, wn = wid >> 2;
    int lrow = lane >> 2, lcol = lane & 3;
    const float scale = 0.17677669529663687f;   // 1/sqrt(32)
    const float L2E = 1.4426950408889634f;

    // ---- stage Q (scaled) raw into P region as [64][36] ----
#pragma unroll
    for (int v = tid; v < 512; v += 256) {
        int r = v >> 3, d0 = (v & 7) * 4;
        float4 qv = *reinterpret_cast<const float4*>(
            &g_q[((size_t)(b*MM) + q0 + r) * CC + h*DD + d0]);
        qv.x *= scale; qv.y *= scale; qv.z *= scale; qv.w *= scale;
        *reinterpret_cast<float4*>(&sP[r*ATT_QP + d0]) = qv;
    }
    __syncthreads();

    // hoist Q fragments to registers (rounded tf32)
    uint32_t Aq[4][4];
    {
        int m = 16*wm + lrow;
#pragma unroll
        for (int ks = 0; ks < 4; ks++) {
            int kf = ks*8 + lcol;
            Aq[ks][0] = tf32u(sP[m*ATT_QP + kf]);
            Aq[ks][1] = tf32u(sP[(m+8)*ATT_QP + kf]);
            Aq[ks][2] = tf32u(sP[m*ATT_QP + kf + 4]);
            Aq[ks][3] = tf32u(sP[(m+8)*ATT_QP + kf + 4]);
        }
    }

    float oacc[2][4];
#pragma unroll
    for (int nt = 0; nt < 2; nt++)
#pragma unroll
        for (int j = 0; j < 4; j++) oacc[nt][j] = 0.f;
    float mrun0 = -1e30f, mrun1 = -1e30f, lrun0 = 0.f, lrun1 = 0.f;
    int rbase = 16*wm + lrow;

    for (int kt = 0; kt < 16; kt++) {
        __syncthreads();
#pragma unroll
        for (int v = tid; v < 512; v += 256) {
            int r = v >> 3, d0 = (v & 7) * 4;
            size_t gi = ((size_t)b*MM + kt*64 + r) * CC + h*DD + d0;
            float4 kv = *reinterpret_cast<const float4*>(&g_kmat[gi]);
            sK[(d0+0)*ATT_KP + r] = kv.x;
            sK[(d0+1)*ATT_KP + r] = kv.y;
            sK[(d0+2)*ATT_KP + r] = kv.z;
            sK[(d0+3)*ATT_KP + r] = kv.w;
            float4 vv = *reinterpret_cast<const float4*>(&g_v[gi]);
            *reinterpret_cast<float4*>(&sV[r*ATT_VP + d0]) = vv;
        }
        __syncthreads();

        // ---- QK^T mma ----
        float s[4][4];
#pragma unroll
        for (int nt = 0; nt < 4; nt++)
#pragma unroll
            for (int j = 0; j < 4; j++) s[nt][j] = 0.f;
#pragma unroll
        for (int ks = 0; ks < 4; ks++) {
            int kf = ks*8 + lcol;
#pragma unroll
            for (int nt = 0; nt < 4; nt++) {
                int key = wn*32 + nt*8 + lrow;
                uint32_t b0 = tf32u(sK[kf*ATT_KP + key]);
                uint32_t b1 = tf32u(sK[(kf+4)*ATT_KP + key]);
                mma8(s[nt], Aq[ks], b0, b1);
            }
        }

        // ---- row max ----
        float t0 = -1e30f, t1 = -1e30f;
#pragma unroll
        for (int nt = 0; nt < 4; nt++) {
            t0 = fmaxf(t0, fmaxf(s[nt][0], s[nt][1]));
            t1 = fmaxf(t1, fmaxf(s[nt][2], s[nt][3]));
        }
        t0 = fmaxf(t0, __shfl_xor_sync(0xffffffff, t0, 1));
        t0 = fmaxf(t0, __shfl_xor_sync(0xffffffff, t0, 2));
        t1 = fmaxf(t1, __shfl_xor_sync(0xffffffff, t1, 1));
        t1 = fmaxf(t1, __shfl_xor_sync(0xffffffff, t1, 2));
        if (lcol == 0) {
            sRm[wn*64 + rbase]     = t0;
            sRm[wn*64 + rbase + 8] = t1;
        }
        __syncthreads();
        float mnew0 = fmaxf(mrun0, fmaxf(sRm[rbase],     sRm[64 + rbase]));
        float mnew1 = fmaxf(mrun1, fmaxf(sRm[rbase + 8], sRm[64 + rbase + 8]));

        // ---- exp, partial sums, write raw P ----
        float ls0 = 0.f, ls1 = 0.f;
#pragma unroll
        for (int nt = 0; nt < 4; nt++) {
            float p0 = exp2f((s[nt][0] - mnew0) * L2E);
            float p1 = exp2f((s[nt][1] - mnew0) * L2E);
            float p2 = exp2f((s[nt][2] - mnew1) * L2E);
            float p3 = exp2f((s[nt][3] - mnew1) * L2E);
            ls0 += p0 + p1;
            ls1 += p2 + p3;
            int col = wn*32 + nt*8 + 2*lcol;
            float2 w0 = {p0, p1}, w1 = {p2, p3};
            *reinterpret_cast<float2*>(&sP[rbase*ATT_PP + col])     = w0;
            *reinterpret_cast<float2*>(&sP[(rbase+8)*ATT_PP + col]) = w1;
        }
        ls0 += __shfl_xor_sync(0xffffffff, ls0, 1);
        ls0 += __shfl_xor_sync(0xffffffff, ls0, 2);
        ls1 += __shfl_xor_sync(0xffffffff, ls1, 1);
        ls1 += __shfl_xor_sync(0xffffffff, ls1, 2);
        if (lcol == 0) {
            sRl[wn*64 + rbase]     = ls0;
            sRl[wn*64 + rbase + 8] = ls1;
        }
        __syncthreads();
        float lt0 = sRl[rbase]     + sRl[64 + rbase];
        float lt1 = sRl[rbase + 8] + sRl[64 + rbase + 8];
        float c0 = exp2f((mrun0 - mnew0) * L2E);
        float c1 = exp2f((mrun1 - mnew1) * L2E);
        lrun0 = lrun0 * c0 + lt0;
        lrun1 = lrun1 * c1 + lt1;
        mrun0 = mnew0; mrun1 = mnew1;
#pragma unroll
        for (int nt = 0; nt < 2; nt++) {
            oacc[nt][0] *= c0; oacc[nt][1] *= c0;
            oacc[nt][2] *= c1; oacc[nt][3] *= c1;
        }

        // ---- P*V mma ----
#pragma unroll
        for (int ks = 0; ks < 8; ks++) {
            int kf = ks*8 + lcol;
            uint32_t Ap[4];
            Ap[0] = tf32u(sP[rbase*ATT_PP + kf]);
            Ap[1] = tf32u(sP[(rbase+8)*ATT_PP + kf]);
            Ap[2] = tf32u(sP[rbase*ATT_PP + kf + 4]);
            Ap[3] = tf32u(sP[(rbase+8)*ATT_PP + kf + 4]);
#pragma unroll
            for (int nt = 0; nt < 2; nt++) {
                int d = wn*16 + nt*8 + lrow;
                uint32_t b0 = tf32u(sV[kf*ATT_VP + d]);
                uint32_t b1 = tf32u(sV[(kf+4)*ATT_VP + d]);
                mma8(oacc[nt], Ap, b0, b1);
            }
        }
    }

    // ---- write output ----
    float i0 = 1.f / lrun0, i1 = 1.f / lrun1;
#pragma unroll
    for (int nt = 0; nt < 2; nt++) {
        int col = h*DD + wn*16 + nt*8 + 2*lcol;
        size_t o0 = ((size_t)(b*MM) + q0 + rbase) * CC + col;
        size_t o1 = ((size_t)(b*MM) + q0 + rbase + 8) * CC + col;
        float2 w0 = {oacc[nt][0]*i0, oacc[nt][1]*i0};
        float2 w1 = {oacc[nt][2]*i1, oacc[nt][3]*i1};
        *reinterpret_cast<float2*>(&g_ao[o0]) = w0;
        *reinterpret_cast<float2*>(&g_ao[o1]) = w1;
    }
}

// ---------------- launch ----------------
extern "C" void kernel_launch(void* const* d_in, const int* in_sizes, int n_in,
                              void* d_out, int out_size)
{
    const float* x       = (const float*)d_in[0];
    const float* mass    = (const float*)d_in[1];
    const float* evals   = (const float*)d_in[2];
    const float* evecs   = (const float*)d_in[3];
    const int*   far_idx = (const int*)  d_in[4];
    const float* t_in    = (const float*)d_in[5];
    const float* t_out   = (const float*)d_in[6];
    const float* gn_w    = (const float*)d_in[7];
    const float* gn_b    = (const float*)d_in[8];
    const float* Wq      = (const float*)d_in[9];
    const float* bq      = (const float*)d_in[10];
    const float* Wk      = (const float*)d_in[11];
    const float* bk      = (const float*)d_in[12];
    const float* Wv      = (const float*)d_in[13];
    const float* bv      = (const float*)d_in[14];
    const float* Wo      = (const float*)d_in[15];
    const float* bo      = (const float*)d_in[16];
    const float* out_w   = (const float*)d_in[17];
    float* out = (float*)d_out;

    static int s_attr_done = 0;
    const int TOB_SMEM  = TOB_SMEM_FLOATS  * 4;
    const int GEMM_SMEM = GEMM_SMEM_FLOATS * 4;
    const int ATT_SMEM  = ATT_SMEM_FLOATS  * 4;
    if (!s_attr_done) {
        cudaFuncSetAttribute(k_tobasis_mma, cudaFuncAttributeMaxDynamicSharedMemorySize, TOB_SMEM);
        cudaFuncSetAttribute(k_gemm_mma,    cudaFuncAttributeMaxDynamicSharedMemorySize, GEMM_SMEM);
        cudaFuncSetAttribute(k_attn_mma,    cudaFuncAttributeMaxDynamicSharedMemorySize, ATT_SMEM);
        s_attr_done = 1;
    }

    float *p_spec1, *p_spec1m, *p_spec2, *p_spec2m, *p_xfar, *p_q, *p_k, *p_v, *p_ao, *p_proj;
    cudaGetSymbolAddress((void**)&p_spec1,  g_spec1);
    cudaGetSymbolAddress((void**)&p_spec1m, g_spec1m);
    cudaGetSymbolAddress((void**)&p_spec2,  g_spec2);
    cudaGetSymbolAddress((void**)&p_spec2m, g_spec2m);
    cudaGetSymbolAddress((void**)&p_xfar,   g_xfar);
    cudaGetSymbolAddress((void**)&p_q,      g_q);
    cudaGetSymbolAddress((void**)&p_k,      g_kmat);
    cudaGetSymbolAddress((void**)&p_v,      g_v);
    cudaGetSymbolAddress((void**)&p_ao,     g_ao);
    cudaGetSymbolAddress((void**)&p_proj,   g_proj);

    const long long AKC = (long long)KK * CC;
    const long long AMC = (long long)MM * CC;
    const long long ANK = (long long)NN * KK;
    const long long ANC = (long long)NN * CC;

    k_zero<<<512, 256>>>();

    // to_basis 1: full N, split-K over 32 chunks of 1024
    k_tobasis_mma<<<dim3(32, 4, BB), 256, TOB_SMEM>>>(x, mass, evecs, nullptr, p_spec1, 1024, NN);
    k_coef<<<BB*KK, CC>>>(evals, t_in, p_spec1, p_spec1m, nullptr);

    // from_basis 1: only the M gathered rows
    k_gemm_mma<<<dim3(MM/128, 4, BB), 256, GEMM_SMEM>>>(
        evecs, far_idx, ANK,
        p_spec1m, nullptr, nullptr, AKC,
        nullptr, nullptr, nullptr,
        p_xfar, nullptr, nullptr, AMC, KK, 1);

    // GroupNorm
    k_gnstats<<<BB*GG, 256>>>();
    k_gnapply<<<(BB*MM*CC/4)/256, 256>>>(gn_w, gn_b);

    // QKV projections fused (nW=3)
    k_gemm_mma<<<dim3(MM/128, 4, BB*3), 256, GEMM_SMEM>>>(
        p_xfar, nullptr, AMC,
        Wq, Wk, Wv, 0,
        bq, bk, bv,
        p_q, p_k, p_v, AMC, CC, 3);

    // attention (tensor-core flash, single-pass tf32)
    k_attn_mma<<<dim3(MM/64, HH, BB), 256, ATT_SMEM>>>();

    // output projection
    k_gemm_mma<<<dim3(MM/128, 4, BB), 256, GEMM_SMEM>>>(
        p_ao, nullptr, AMC,
        Wo, nullptr, nullptr, 0,
        bo, nullptr, nullptr,
        p_proj, nullptr, nullptr, AMC, CC, 1);

    // to_basis 2: only the M scattered rows
    k_tobasis_mma<<<dim3(8, 4, BB), 256, TOB_SMEM>>>(p_proj, mass, evecs, far_idx, p_spec2, 128, MM);
    k_coef<<<BB*KK, CC>>>(evals, t_out, p_spec2, p_spec2m, out_w);

    // from_basis 2: full N output (out_w folded into spec2m)
    k_gemm_mma<<<dim3(NN/128, 4, BB), 256, GEMM_SMEM>>>(
        evecs, nullptr, ANK,
        p_spec2m, nullptr, nullptr, AKC,
        nullptr, nullptr, nullptr,
        out, nullptr, nullptr, ANC, KK, 1);
}

// round 16
// speedup vs baseline: 1.6395x; 1.4938x over previous
#include <cuda_runtime.h>
#include <math.h>
#include <stdint.h>

#define BB 4
#define NN 32768
#define KK 128
#define MM 1024
#define CC 256
#define GG 32
#define HH 8
#define DD 32

// ---------------- scratch (device globals; no allocation allowed) ----------------
__device__ float g_spec1 [BB*KK*CC];
__device__ float g_spec1m[BB*KK*CC];
__device__ float g_spec2 [BB*KK*CC];
__device__ float g_spec2m[BB*KK*CC];
__device__ float g_xfar  [BB*MM*CC];
__device__ float g_q     [BB*MM*CC];
__device__ float g_kmat  [BB*MM*CC];
__device__ float g_v     [BB*MM*CC];
__device__ float g_ao    [BB*MM*CC];
__device__ float g_proj  [BB*MM*CC];
__device__ float g_gnm   [BB*GG];
__device__ float g_gnr   [BB*GG];

// ---------------- tf32 / cp.async helpers ----------------
__device__ __forceinline__ uint32_t tf32u(float x) {
    uint32_t u; asm("cvt.rna.tf32.f32 %0, %1;" : "=r"(u) : "f"(x));
    return u;
}

__device__ __forceinline__ void mma8(float d[4], const uint32_t a[4],
                                     uint32_t b0, uint32_t b1) {
    asm volatile(
        "mma.sync.aligned.m16n8k8.row.col.f32.tf32.tf32.f32 "
        "{%0,%1,%2,%3},{%4,%5,%6,%7},{%8,%9},{%0,%1,%2,%3};\n"
        : "+f"(d[0]), "+f"(d[1]), "+f"(d[2]), "+f"(d[3])
        : "r"(a[0]), "r"(a[1]), "r"(a[2]), "r"(a[3]), "r"(b0), "r"(b1));
}

__device__ __forceinline__ void cpa16(const float* smem_ptr, const float* gptr) {
    uint32_t s = (uint32_t)__cvta_generic_to_shared(smem_ptr);
    asm volatile("cp.async.cg.shared.global [%0], [%1], 16;\n" :: "r"(s), "l"(gptr));
}
__device__ __forceinline__ void cpa4(const float* smem_ptr, const float* gptr) {
    uint32_t s = (uint32_t)__cvta_generic_to_shared(smem_ptr);
    asm volatile("cp.async.ca.shared.global [%0], [%1], 4;\n" :: "r"(s), "l"(gptr));
}
#define CPA_COMMIT() asm volatile("cp.async.commit_group;\n" ::: "memory")
#define CPA_WAIT0()  asm volatile("cp.async.wait_group 0;\n" ::: "memory")

// ---------------- zero the atomic accumulators ----------------
__global__ void k_zero() {
    int i = blockIdx.x * blockDim.x + threadIdx.x;
    if (i < BB*KK*CC) { g_spec1[i] = 0.f; g_spec2[i] = 0.f; }
}

// =====================================================================
// to_basis via single-pass tf32 mma, cp.async pipeline, 32-deep K-chunks.
// spec[b,k,c] += sum_n E[b,row(n),k] * mass[row] * X[b,n,c]
// smem: E raw [2][32][136] ([n][k]), X raw [2][32][72], mass [2][32]
// mass applied at fragment load (fp32 mul then tf32 round — bit-identical
// to pre-scaled staging).
// =====================================================================
#define TOB_SMEM_FLOATS (2*32*136 + 2*32*72 + 64)   // 13376 floats = 53504 B

__global__ void __launch_bounds__(256,2) k_tobasis_mma(
    const float* __restrict__ X, const float* __restrict__ mass,
    const float* __restrict__ evecs, const int* __restrict__ gidx,
    float* __restrict__ spec, int chunk, int xRowsPerBatch)
{
    extern __shared__ float sm[];
    float* sE = sm;                 // [2][32][136]
    float* sX = sE + 2*32*136;      // [2][32][72]
    float* sM = sX + 2*32*72;       // [2][32]
#define SE(bf,r,c) sE[(bf)*4352 + (r)*136 + (c)]
#define SX(bf,r,c) sX[(bf)*2304 + (r)*72 + (c)]
#define SMS(bf,r)  sM[(bf)*32 + (r)]

    int b  = blockIdx.z;
    int c0 = blockIdx.y * 64;
    int n0 = blockIdx.x * chunk;
    int tid  = threadIdx.x;
    int wid  = tid >> 5, lane = tid & 31;
    int wm   = wid & 3;
    int wn   = wid >> 2;
    int lrow = lane >> 2;
    int lcol = lane & 3;

    int iters = chunk >> 5;

    int er[4], ec[4];
#pragma unroll
    for (int j = 0; j < 4; j++) { int f = tid + j*256; er[j] = f >> 5; ec[j] = (f & 31) * 4; }
    int xr[2], xc[2];
#pragma unroll
    for (int j = 0; j < 2; j++) { int f = tid + j*256; xr[j] = f >> 4; xc[j] = (f & 15) * 4; }

#define TOB_CPA(it, bf) {                                                      \
        int nb = (it) << 5;                                                    \
        _Pragma("unroll")                                                      \
        for (int j = 0; j < 4; j++) {                                          \
            int n = n0 + nb + er[j];                                           \
            int rr = gidx ? gidx[b*MM + n] : n;                                \
            cpa16(&SE(bf, er[j], ec[j]), &evecs[((size_t)b*NN + rr)*KK + ec[j]]); \
        }                                                                      \
        _Pragma("unroll")                                                      \
        for (int j = 0; j < 2; j++) {                                          \
            int n = n0 + nb + xr[j];                                           \
            cpa16(&SX(bf, xr[j], xc[j]), &X[((size_t)b*xRowsPerBatch + n)*CC + c0 + xc[j]]); \
        }                                                                      \
        if (tid < 32) {                                                        \
            int n = n0 + nb + tid;                                             \
            int rr = gidx ? gidx[b*MM + n] : n;                                \
            cpa4(&SMS(bf, tid), &mass[(size_t)b*NN + rr]);                     \
        }                                                                      \
        CPA_COMMIT();                                                          \
    }

    float acc[2][4][4];
#pragma unroll
    for (int mt = 0; mt < 2; mt++)
#pragma unroll
        for (int nt = 0; nt < 4; nt++)
#pragma unroll
            for (int j = 0; j < 4; j++) acc[mt][nt][j] = 0.f;

    TOB_CPA(0, 0);

    for (int i = 0; i < iters; i++) {
        int cur = i & 1;
        CPA_WAIT0();
        __syncthreads();
        if (i + 1 < iters) TOB_CPA(i + 1, cur ^ 1);

#pragma unroll
        for (int ks = 0; ks < 4; ks++) {
            int kf = ks*8 + lcol;
            float m0 = SMS(cur, kf), m1 = SMS(cur, kf+4);
            uint32_t Af[2][4];
#pragma unroll
            for (int mt = 0; mt < 2; mt++) {
                int m = wm*32 + mt*16 + lrow;
                Af[mt][0] = tf32u(SE(cur, kf,   m));
                Af[mt][1] = tf32u(SE(cur, kf,   m+8));
                Af[mt][2] = tf32u(SE(cur, kf+4, m));
                Af[mt][3] = tf32u(SE(cur, kf+4, m+8));
            }
#pragma unroll
            for (int nt = 0; nt < 4; nt++) {
                int c = wn*32 + nt*8 + lrow;
                uint32_t b0 = tf32u(SX(cur, kf,   c) * m0);
                uint32_t b1 = tf32u(SX(cur, kf+4, c) * m1);
#pragma unroll
                for (int mt = 0; mt < 2; mt++)
                    mma8(acc[mt][nt], Af[mt], b0, b1);
            }
        }
    }

#pragma unroll
    for (int mt = 0; mt < 2; mt++) {
#pragma unroll
        for (int nt = 0; nt < 4; nt++) {
            int row0 = wm*32 + mt*16 + lrow;
            int col  = c0 + wn*32 + nt*8 + 2*lcol;
            float* p0 = &spec[((size_t)b*KK + row0    ) * CC + col];
            float* p1 = &spec[((size_t)b*KK + row0 + 8) * CC + col];
            atomicAdd(p0,     acc[mt][nt][0]);
            atomicAdd(p0 + 1, acc[mt][nt][1]);
            atomicAdd(p1,     acc[mt][nt][2]);
            atomicAdd(p1 + 1, acc[mt][nt][3]);
        }
    }
}

// =====================================================================
// generic single-pass tf32 mma GEMM, cp.async pipeline, 32-deep K-chunks.
// smem: A raw [2][128][36], B raw [2][32][72]
// =====================================================================
#define GEMM_SMEM_FLOATS (2*128*36 + 2*32*72)   // 13824 floats = 55296 B

__global__ void __launch_bounds__(256,2) k_gemm_mma(
    const float* __restrict__ A, const int* __restrict__ gidx, long long aBatch,
    const float* __restrict__ W0, const float* __restrict__ W1,
    const float* __restrict__ W2, long long wBatch,
    const float* __restrict__ bias0, const float* __restrict__ bias1,
    const float* __restrict__ bias2,
    float* __restrict__ out0, float* __restrict__ out1, float* __restrict__ out2,
    long long oBatch, int Kd, int nW)
{
    extern __shared__ float sm[];
    float* sA = sm;                 // [2][128][36]
    float* sB = sA + 2*128*36;      // [2][32][72]
#define SA(bf,r,k) sA[(bf)*4608 + (r)*36 + (k)]
#define SB(bf,r,c) sB[(bf)*2304 + (r)*72 + (c)]

    int z   = blockIdx.z;
    int b   = z / nW;
    int sel = z - b * nW;
    int r0  = blockIdx.x * 128;
    int c0  = blockIdx.y * 64;

    const float* W    = (sel == 0) ? W0    : (sel == 1) ? W1    : W2;
    const float* bias = (sel == 0) ? bias0 : (sel == 1) ? bias1 : bias2;
    float*       out  = (sel == 0) ? out0  : (sel == 1) ? out1  : out2;

    int tid  = threadIdx.x;
    int wid  = tid >> 5, lane = tid & 31;
    int wm   = wid & 3;
    int wn   = wid >> 2;
    int lrow = lane >> 2;
    int lcol = lane & 3;

    const float* Ab = A + (size_t)b * aBatch;
    const float* Wb = W + (size_t)b * wBatch;
    float*       Ob = out + (size_t)b * oBatch;

    int iters = Kd >> 5;

    int ar[4], ak[4], ga[4];
#pragma unroll
    for (int j = 0; j < 4; j++) {
        int f = tid + j*256;
        ar[j] = f >> 3; ak[j] = (f & 7) * 4;
        ga[j] = gidx ? gidx[b*MM + r0 + ar[j]] : (r0 + ar[j]);
    }
    int br[2], bc[2];
#pragma unroll
    for (int j = 0; j < 2; j++) { int f = tid + j*256; br[j] = f >> 4; bc[j] = (f & 15) * 4; }

#define G_CPA(it, bf) {                                                        \
        int kc = (it) << 5;                                                    \
        _Pragma("unroll")                                                      \
        for (int j = 0; j < 4; j++)                                            \
            cpa16(&SA(bf, ar[j], ak[j]), Ab + (size_t)ga[j] * Kd + kc + ak[j]); \
        _Pragma("unroll")                                                      \
        for (int j = 0; j < 2; j++)                                            \
            cpa16(&SB(bf, br[j], bc[j]), Wb + (size_t)(kc + br[j]) * CC + c0 + bc[j]); \
        CPA_COMMIT();                                                          \
    }

    float acc[2][4][4];
#pragma unroll
    for (int mt = 0; mt < 2; mt++)
#pragma unroll
        for (int nt = 0; nt < 4; nt++)
#pragma unroll
            for (int j = 0; j < 4; j++) acc[mt][nt][j] = 0.f;

    G_CPA(0, 0);

    for (int i = 0; i < iters; i++) {
        int cur = i & 1;
        CPA_WAIT0();
        __syncthreads();
        if (i + 1 < iters) G_CPA(i + 1, cur ^ 1);

#pragma unroll
        for (int ks = 0; ks < 4; ks++) {
            int kf = ks*8 + lcol;
            uint32_t Af[2][4];
#pragma unroll
            for (int mt = 0; mt < 2; mt++) {
                int m = wm*32 + mt*16 + lrow;
                Af[mt][0] = tf32u(SA(cur, m,   kf));
                Af[mt][1] = tf32u(SA(cur, m+8, kf));
                Af[mt][2] = tf32u(SA(cur, m,   kf+4));
                Af[mt][3] = tf32u(SA(cur, m+8, kf+4));
            }
#pragma unroll
            for (int nt = 0; nt < 4; nt++) {
                int c = wn*32 + nt*8 + lrow;
                uint32_t b0 = tf32u(SB(cur, kf,   c));
                uint32_t b1 = tf32u(SB(cur, kf+4, c));
#pragma unroll
                for (int mt = 0; mt < 2; mt++)
                    mma8(acc[mt][nt], Af[mt], b0, b1);
            }
        }
    }

#pragma unroll
    for (int mt = 0; mt < 2; mt++) {
#pragma unroll
        for (int nt = 0; nt < 4; nt++) {
            int row0 = r0 + wm*32 + mt*16 + lrow;
            int col  = c0 + wn*32 + nt*8 + 2*lcol;
            float b0v = bias ? bias[col]     : 0.f;
            float b1v = bias ? bias[col + 1] : 0.f;
            float2 v0 = {acc[mt][nt][0] + b0v, acc[mt][nt][1] + b1v};
            float2 v1 = {acc[mt][nt][2] + b0v, acc[mt][nt][3] + b1v};
            *reinterpret_cast<float2*>(&Ob[(size_t)row0       * CC + col]) = v0;
            *reinterpret_cast<float2*>(&Ob[(size_t)(row0 + 8) * CC + col]) = v1;
        }
    }
}

// ---------------- spectral coefficient multiply (+ optional out_w fold) ----------------
__global__ void k_coef(const float* __restrict__ evals, const float* __restrict__ tvec,
                       const float* __restrict__ specin, float* __restrict__ specout,
                       const float* __restrict__ outw)
{
    int bk = blockIdx.x;
    int b = bk >> 7, k = bk & 127;
    int c = threadIdx.x;
    float t = fmaxf(tvec[c], 1e-8f);
    float w = outw ? fmaxf(outw[c], 1e-8f) : 1.f;
    specout[(size_t)bk*CC + c] = expf(-evals[b*KK + k] * t) * specin[(size_t)bk*CC + c] * w;
}

// ---------------- GroupNorm stats ----------------
__global__ void k_gnstats()
{
    int b = blockIdx.x >> 5, g = blockIdx.x & 31;
    int tid = threadIdx.x;
    float s = 0.f, s2 = 0.f;
    for (int e = tid; e < MM*8; e += 256) {
        int m = e >> 3, j = e & 7;
        float v = g_xfar[((size_t)(b*MM + m)) * CC + (g << 3) + j];
        s += v; s2 += v * v;
    }
    __shared__ float rs[256], rq[256];
    rs[tid] = s; rq[tid] = s2;
    __syncthreads();
    for (int o = 128; o > 0; o >>= 1) {
        if (tid < o) { rs[tid] += rs[tid+o]; rq[tid] += rq[tid+o]; }
        __syncthreads();
    }
    if (tid == 0) {
        float mean = rs[0] * (1.f/8192.f);
        float var  = rq[0] * (1.f/8192.f) - mean*mean;
        g_gnm[blockIdx.x] = mean;
        g_gnr[blockIdx.x] = rsqrtf(var + 1e-6f);
    }
}

// ---------------- GroupNorm apply (in place) ----------------
__global__ void k_gnapply(const float* __restrict__ gn_w, const float* __restrict__ gn_b)
{
    int i = blockIdx.x * blockDim.x + threadIdx.x;
    int base = i * 4;
    int c  = base & 255;
    int bm = base >> 8;
    int b  = bm >> 10;
    int g  = c >> 3;
    float mean = g_gnm[b*GG + g];
    float r    = g_gnr[b*GG + g];
    float4 v = *reinterpret_cast<float4*>(&g_xfar[base]);
    v.x = (v.x - mean) * r * gn_w[c+0] + gn_b[c+0];
    v.y = (v.y - mean) * r * gn_w[c+1] + gn_b[c+1];
    v.z = (v.z - mean) * r * gn_w[c+2] + gn_b[c+2];
    v.w = (v.w - mean) * r * gn_w[c+3] + gn_b[c+3];
    *reinterpret_cast<float4*>(&g_xfar[base]) = v;
}

// =====================================================================
// flash attention with single-pass tf32 mma, raw-fp32 smem.
// (unchanged from round 14 — protected win)
// =====================================================================
#define ATT_KP 69
#define ATT_VP 40
#define ATT_PP 68
#define ATT_QP 36
#define ATT_SMEM_FLOATS (32*ATT_KP + 64*ATT_VP + 64*ATT_PP + 256)   // 9376 floats

__global__ void __launch_bounds__(256,2) k_attn_mma()
{
    extern __shared__ float sm[];
    float* sK  = sm;                        // [32][69] raw, transposed [d][key]
    float* sV  = sK + 32*ATT_KP;            // [64][40] raw
    float* sP  = sV + 64*ATT_VP;            // [64][68] raw (Q staging [64][36])
    float* sRm = sP + 64*ATT_PP;            // [2][64]
    float* sRl = sRm + 128;                 // [2][64]

    int b = blockIdx.z, h = blockIdx.y, q0 = blockIdx.x * 64;
    int tid = threadIdx.x;
    int wid = tid >> 5, lane = tid & 31;
    int wm = wid & 3, wn = wid >> 2;
    int lrow = lane >> 2, lcol = lane & 3;
    const float scale = 0.17677669529663687f;   // 1/sqrt(32)
    const float L2E = 1.4426950408889634f;

#pragma unroll
    for (int v = tid; v < 512; v += 256) {
        int r = v >> 3, d0 = (v & 7) * 4;
        float4 qv = *reinterpret_cast<const float4*>(
            &g_q[((size_t)(b*MM) + q0 + r) * CC + h*DD + d0]);
        qv.x *= scale; qv.y *= scale; qv.z *= scale; qv.w *= scale;
        *reinterpret_cast<float4*>(&sP[r*ATT_QP + d0]) = qv;
    }
    __syncthreads();

    uint32_t Aq[4][4];
    {
        int m = 16*wm + lrow;
#pragma unroll
        for (int ks = 0; ks < 4; ks++) {
            int kf = ks*8 + lcol;
            Aq[ks][0] = tf32u(sP[m*ATT_QP + kf]);
            Aq[ks][1] = tf32u(sP[(m+8)*ATT_QP + kf]);
            Aq[ks][2] = tf32u(sP[m*ATT_QP + kf + 4]);
            Aq[ks][3] = tf32u(sP[(m+8)*ATT_QP + kf + 4]);
        }
    }

    float oacc[2][4];
#pragma unroll
    for (int nt = 0; nt < 2; nt++)
#pragma unroll
        for (int j = 0; j < 4; j++) oacc[nt][j] = 0.f;
    float mrun0 = -1e30f, mrun1 = -1e30f, lrun0 = 0.f, lrun1 = 0.f;
    int rbase = 16*wm + lrow;

    for (int kt = 0; kt < 16; kt++) {
        __syncthreads();
#pragma unroll
        for (int v = tid; v < 512; v += 256) {
            int r = v >> 3, d0 = (v & 7) * 4;
            size_t gi = ((size_t)b*MM + kt*64 + r) * CC + h*DD + d0;
            float4 kv = *reinterpret_cast<const float4*>(&g_kmat[gi]);
            sK[(d0+0)*ATT_KP + r] = kv.x;
            sK[(d0+1)*ATT_KP + r] = kv.y;
            sK[(d0+2)*ATT_KP + r] = kv.z;
            sK[(d0+3)*ATT_KP + r] = kv.w;
            float4 vv = *reinterpret_cast<const float4*>(&g_v[gi]);
            *reinterpret_cast<float4*>(&sV[r*ATT_VP + d0]) = vv;
        }
        __syncthreads();

        float s[4][4];
#pragma unroll
        for (int nt = 0; nt < 4; nt++)
#pragma unroll
            for (int j = 0; j < 4; j++) s[nt][j] = 0.f;
#pragma unroll
        for (int ks = 0; ks < 4; ks++) {
            int kf = ks*8 + lcol;
#pragma unroll
            for (int nt = 0; nt < 4; nt++) {
                int key = wn*32 + nt*8 + lrow;
                uint32_t b0 = tf32u(sK[kf*ATT_KP + key]);
                uint32_t b1 = tf32u(sK[(kf+4)*ATT_KP + key]);
                mma8(s[nt], Aq[ks], b0, b1);
            }
        }

        float t0 = -1e30f, t1 = -1e30f;
#pragma unroll
        for (int nt = 0; nt < 4; nt++) {
            t0 = fmaxf(t0, fmaxf(s[nt][0], s[nt][1]));
            t1 = fmaxf(t1, fmaxf(s[nt][2], s[nt][3]));
        }
        t0 = fmaxf(t0, __shfl_xor_sync(0xffffffff, t0, 1));
        t0 = fmaxf(t0, __shfl_xor_sync(0xffffffff, t0, 2));
        t1 = fmaxf(t1, __shfl_xor_sync(0xffffffff, t1, 1));
        t1 = fmaxf(t1, __shfl_xor_sync(0xffffffff, t1, 2));
        if (lcol == 0) {
            sRm[wn*64 + rbase]     = t0;
            sRm[wn*64 + rbase + 8] = t1;
        }
        __syncthreads();
        float mnew0 = fmaxf(mrun0, fmaxf(sRm[rbase],     sRm[64 + rbase]));
        float mnew1 = fmaxf(mrun1, fmaxf(sRm[rbase + 8], sRm[64 + rbase + 8]));

        float ls0 = 0.f, ls1 = 0.f;
#pragma unroll
        for (int nt = 0; nt < 4; nt++) {
            float p0 = exp2f((s[nt][0] - mnew0) * L2E);
            float p1 = exp2f((s[nt][1] - mnew0) * L2E);
            float p2 = exp2f((s[nt][2] - mnew1) * L2E);
            float p3 = exp2f((s[nt][3] - mnew1) * L2E);
            ls0 += p0 + p1;
            ls1 += p2 + p3;
            int col = wn*32 + nt*8 + 2*lcol;
            float2 w0 = {p0, p1}, w1 = {p2, p3};
            *reinterpret_cast<float2*>(&sP[rbase*ATT_PP + col])     = w0;
            *reinterpret_cast<float2*>(&sP[(rbase+8)*ATT_PP + col]) = w1;
        }
        ls0 += __shfl_xor_sync(0xffffffff, ls0, 1);
        ls0 += __shfl_xor_sync(0xffffffff, ls0, 2);
        ls1 += __shfl_xor_sync(0xffffffff, ls1, 1);
        ls1 += __shfl_xor_sync(0xffffffff, ls1, 2);
        if (lcol == 0) {
            sRl[wn*64 + rbase]     = ls0;
            sRl[wn*64 + rbase + 8] = ls1;
        }
        __syncthreads();
        float lt0 = sRl[rbase]     + sRl[64 + rbase];
        float lt1 = sRl[rbase + 8] + sRl[64 + rbase + 8];
        float c0 = exp2f((mrun0 - mnew0) * L2E);
        float c1 = exp2f((mrun1 - mnew1) * L2E);
        lrun0 = lrun0 * c0 + lt0;
        lrun1 = lrun1 * c1 + lt1;
        mrun0 = mnew0; mrun1 = mnew1;
#pragma unroll
        for (int nt = 0; nt < 2; nt++) {
            oacc[nt][0] *= c0; oacc[nt][1] *= c0;
            oacc[nt][2] *= c1; oacc[nt][3] *= c1;
        }

#pragma unroll
        for (int ks = 0; ks < 8; ks++) {
            int kf = ks*8 + lcol;
            uint32_t Ap[4];
            Ap[0] = tf32u(sP[rbase*ATT_PP + kf]);
            Ap[1] = tf32u(sP[(rbase+8)*ATT_PP + kf]);
            Ap[2] = tf32u(sP[rbase*ATT_PP + kf + 4]);
            Ap[3] = tf32u(sP[(rbase+8)*ATT_PP + kf + 4]);
#pragma unroll
            for (int nt = 0; nt < 2; nt++) {
                int d = wn*16 + nt*8 + lrow;
                uint32_t b0 = tf32u(sV[kf*ATT_VP + d]);
                uint32_t b1 = tf32u(sV[(kf+4)*ATT_VP + d]);
                mma8(oacc[nt], Ap, b0, b1);
            }
        }
    }

    float i0 = 1.f / lrun0, i1 = 1.f / lrun1;
#pragma unroll
    for (int nt = 0; nt < 2; nt++) {
        int col = h*DD + wn*16 + nt*8 + 2*lcol;
        size_t o0 = ((size_t)(b*MM) + q0 + rbase) * CC + col;
        size_t o1 = ((size_t)(b*MM) + q0 + rbase + 8) * CC + col;
        float2 w0 = {oacc[nt][0]*i0, oacc[nt][1]*i0};
        float2 w1 = {oacc[nt][2]*i1, oacc[nt][3]*i1};
        *reinterpret_cast<float2*>(&g_ao[o0]) = w0;
        *reinterpret_cast<float2*>(&g_ao[o1]) = w1;
    }
}

// ---------------- launch ----------------
extern "C" void kernel_launch(void* const* d_in, const int* in_sizes, int n_in,
                              void* d_out, int out_size)
{
    const float* x       = (const float*)d_in[0];
    const float* mass    = (const float*)d_in[1];
    const float* evals   = (const float*)d_in[2];
    const float* evecs   = (const float*)d_in[3];
    const int*   far_idx = (const int*)  d_in[4];
    const float* t_in    = (const float*)d_in[5];
    const float* t_out   = (const float*)d_in[6];
    const float* gn_w    = (const float*)d_in[7];
    const float* gn_b    = (const float*)d_in[8];
    const float* Wq      = (const float*)d_in[9];
    const float* bq      = (const float*)d_in[10];
    const float* Wk      = (const float*)d_in[11];
    const float* bk      = (const float*)d_in[12];
    const float* Wv      = (const float*)d_in[13];
    const float* bv      = (const float*)d_in[14];
    const float* Wo      = (const float*)d_in[15];
    const float* bo      = (const float*)d_in[16];
    const float* out_w   = (const float*)d_in[17];
    float* out = (float*)d_out;

    static int s_attr_done = 0;
    const int TOB_SMEM  = TOB_SMEM_FLOATS  * 4;
    const int GEMM_SMEM = GEMM_SMEM_FLOATS * 4;
    const int ATT_SMEM  = ATT_SMEM_FLOATS  * 4;
    if (!s_attr_done) {
        cudaFuncSetAttribute(k_tobasis_mma, cudaFuncAttributeMaxDynamicSharedMemorySize, TOB_SMEM);
        cudaFuncSetAttribute(k_gemm_mma,    cudaFuncAttributeMaxDynamicSharedMemorySize, GEMM_SMEM);
        cudaFuncSetAttribute(k_attn_mma,    cudaFuncAttributeMaxDynamicSharedMemorySize, ATT_SMEM);
        s_attr_done = 1;
    }

    float *p_spec1, *p_spec1m, *p_spec2, *p_spec2m, *p_xfar, *p_q, *p_k, *p_v, *p_ao, *p_proj;
    cudaGetSymbolAddress((void**)&p_spec1,  g_spec1);
    cudaGetSymbolAddress((void**)&p_spec1m, g_spec1m);
    cudaGetSymbolAddress((void**)&p_spec2,  g_spec2);
    cudaGetSymbolAddress((void**)&p_spec2m, g_spec2m);
    cudaGetSymbolAddress((void**)&p_xfar,   g_xfar);
    cudaGetSymbolAddress((void**)&p_q,      g_q);
    cudaGetSymbolAddress((void**)&p_k,      g_kmat);
    cudaGetSymbolAddress((void**)&p_v,      g_v);
    cudaGetSymbolAddress((void**)&p_ao,     g_ao);
    cudaGetSymbolAddress((void**)&p_proj,   g_proj);

    const long long AKC = (long long)KK * CC;
    const long long AMC = (long long)MM * CC;
    const long long ANK = (long long)NN * KK;
    const long long ANC = (long long)NN * CC;

    k_zero<<<512, 256>>>();

    // to_basis 1: full N, split-K over 32 chunks of 1024
    k_tobasis_mma<<<dim3(32, 4, BB), 256, TOB_SMEM>>>(x, mass, evecs, nullptr, p_spec1, 1024, NN);
    k_coef<<<BB*KK, CC>>>(evals, t_in, p_spec1, p_spec1m, nullptr);

    // from_basis 1: only the M gathered rows
    k_gemm_mma<<<dim3(MM/128, 4, BB), 256, GEMM_SMEM>>>(
        evecs, far_idx, ANK,
        p_spec1m, nullptr, nullptr, AKC,
        nullptr, nullptr, nullptr,
        p_xfar, nullptr, nullptr, AMC, KK, 1);

    // GroupNorm
    k_gnstats<<<BB*GG, 256>>>();
    k_gnapply<<<(BB*MM*CC/4)/256, 256>>>(gn_w, gn_b);

    // QKV projections fused (nW=3)
    k_gemm_mma<<<dim3(MM/128, 4, BB*3), 256, GEMM_SMEM>>>(
        p_xfar, nullptr, AMC,
        Wq, Wk, Wv, 0,
        bq, bk, bv,
        p_q, p_k, p_v, AMC, CC, 3);

    // attention (tensor-core flash, single-pass tf32)
    k_attn_mma<<<dim3(MM/64, HH, BB), 256, ATT_SMEM>>>();

    // output projection
    k_gemm_mma<<<dim3(MM/128, 4, BB), 256, GEMM_SMEM>>>(
        p_ao, nullptr, AMC,
        Wo, nullptr, nullptr, 0,
        bo, nullptr, nullptr,
        p_proj, nullptr, nullptr, AMC, CC, 1);

    // to_basis 2: only the M scattered rows
    k_tobasis_mma<<<dim3(8, 4, BB), 256, TOB_SMEM>>>(p_proj, mass, evecs, far_idx, p_spec2, 128, MM);
    k_coef<<<BB*KK, CC>>>(evals, t_out, p_spec2, p_spec2m, out_w);

    // from_basis 2: full N output (out_w folded into spec2m)
    k_gemm_mma<<<dim3(NN/128, 4, BB), 256, GEMM_SMEM>>>(
        evecs, nullptr, ANK,
        p_spec2m, nullptr, nullptr, AKC,
        nullptr, nullptr, nullptr,
        out, nullptr, nullptr, ANC, KK, 1);
}

// round 17
// speedup vs baseline: 1.6719x; 1.0198x over previous
#include <cuda_runtime.h>
#include <math.h>
#include <stdint.h>

#define BB 4
#define NN 32768
#define KK 128
#define MM 1024
#define CC 256
#define GG 32
#define HH 8
#define DD 32

// ---------------- scratch (device globals; no allocation allowed) ----------------
__device__ float g_spec1 [BB*KK*CC];
__device__ float g_spec1m[BB*KK*CC];
__device__ float g_spec2 [BB*KK*CC];
__device__ float g_spec2m[BB*KK*CC];
__device__ float g_xfar  [BB*MM*CC];
__device__ float g_q     [BB*MM*CC];
__device__ float g_kmat  [BB*MM*CC];
__device__ float g_v     [BB*MM*CC];
__device__ float g_ao    [BB*MM*CC];
__device__ float g_proj  [BB*MM*CC];
__device__ float g_gnm   [BB*GG];
__device__ float g_gnr   [BB*GG];

// ---------------- tf32 / cp.async helpers ----------------
__device__ __forceinline__ uint32_t tf32u(float x) {
    uint32_t u; asm("cvt.rna.tf32.f32 %0, %1;" : "=r"(u) : "f"(x));
    return u;
}

__device__ __forceinline__ void mma8(float d[4], const uint32_t a[4],
                                     uint32_t b0, uint32_t b1) {
    asm volatile(
        "mma.sync.aligned.m16n8k8.row.col.f32.tf32.tf32.f32 "
        "{%0,%1,%2,%3},{%4,%5,%6,%7},{%8,%9},{%0,%1,%2,%3};\n"
        : "+f"(d[0]), "+f"(d[1]), "+f"(d[2]), "+f"(d[3])
        : "r"(a[0]), "r"(a[1]), "r"(a[2]), "r"(a[3]), "r"(b0), "r"(b1));
}

__device__ __forceinline__ void cpa16(const float* smem_ptr, const float* gptr) {
    uint32_t s = (uint32_t)__cvta_generic_to_shared(smem_ptr);
    asm volatile("cp.async.cg.shared.global [%0], [%1], 16;\n" :: "r"(s), "l"(gptr));
}
__device__ __forceinline__ void cpa4(const float* smem_ptr, const float* gptr) {
    uint32_t s = (uint32_t)__cvta_generic_to_shared(smem_ptr);
    asm volatile("cp.async.ca.shared.global [%0], [%1], 4;\n" :: "r"(s), "l"(gptr));
}
#define CPA_COMMIT() asm volatile("cp.async.commit_group;\n" ::: "memory")
#define CPA_WAIT0()  asm volatile("cp.async.wait_group 0;\n" ::: "memory")
#define CPA_WAIT1()  asm volatile("cp.async.wait_group 1;\n" ::: "memory")

// ---------------- zero the atomic accumulators ----------------
__global__ void k_zero() {
    int i = blockIdx.x * blockDim.x + threadIdx.x;
    if (i < BB*KK*CC) { g_spec1[i] = 0.f; g_spec2[i] = 0.f; }
}

// =====================================================================
// to_basis via single-pass tf32 mma, 3-stage cp.async ring, 32-deep chunks.
// spec[b,k,c] += sum_n E[b,row(n),k] * mass[row] * X[b,n,c]
// smem per stage: E raw [32][136] ([n][k]), X raw [32][72], mass [32]
// =====================================================================
#define TOB_STAGE (32*136 + 32*72 + 32)             // 6688 floats
#define TOB_SMEM_FLOATS (3*TOB_STAGE)               // 20064 floats = 80256 B

__global__ void __launch_bounds__(256,2) k_tobasis_mma(
    const float* __restrict__ X, const float* __restrict__ mass,
    const float* __restrict__ evecs, const int* __restrict__ gidx,
    float* __restrict__ spec, int chunk, int xRowsPerBatch)
{
    extern __shared__ float sm[];
#define SE(bf,r,c) sm[(bf)*TOB_STAGE + (r)*136 + (c)]
#define SX(bf,r,c) sm[(bf)*TOB_STAGE + 32*136 + (r)*72 + (c)]
#define SMS(bf,r)  sm[(bf)*TOB_STAGE + 32*136 + 32*72 + (r)]

    int b  = blockIdx.z;
    int c0 = blockIdx.y * 64;
    int n0 = blockIdx.x * chunk;
    int tid  = threadIdx.x;
    int wid  = tid >> 5, lane = tid & 31;
    int wm   = wid & 3;
    int wn   = wid >> 2;
    int lrow = lane >> 2;
    int lcol = lane & 3;

    int iters = chunk >> 5;

    int er[4], ec[4];
#pragma unroll
    for (int j = 0; j < 4; j++) { int f = tid + j*256; er[j] = f >> 5; ec[j] = (f & 31) * 4; }
    int xr[2], xc[2];
#pragma unroll
    for (int j = 0; j < 2; j++) { int f = tid + j*256; xr[j] = f >> 4; xc[j] = (f & 15) * 4; }

#define TOB_CPA(it, bf) {                                                      \
        int nb = (it) << 5;                                                    \
        _Pragma("unroll")                                                      \
        for (int j = 0; j < 4; j++) {                                          \
            int n = n0 + nb + er[j];                                           \
            int rr = gidx ? gidx[b*MM + n] : n;                                \
            cpa16(&SE(bf, er[j], ec[j]), &evecs[((size_t)b*NN + rr)*KK + ec[j]]); \
        }                                                                      \
        _Pragma("unroll")                                                      \
        for (int j = 0; j < 2; j++) {                                          \
            int n = n0 + nb + xr[j];                                           \
            cpa16(&SX(bf, xr[j], xc[j]), &X[((size_t)b*xRowsPerBatch + n)*CC + c0 + xc[j]]); \
        }                                                                      \
        if (tid < 32) {                                                        \
            int n = n0 + nb + tid;                                             \
            int rr = gidx ? gidx[b*MM + n] : n;                                \
            cpa4(&SMS(bf, tid), &mass[(size_t)b*NN + rr]);                     \
        }                                                                      \
        CPA_COMMIT();                                                          \
    }

    float acc[2][4][4];
#pragma unroll
    for (int mt = 0; mt < 2; mt++)
#pragma unroll
        for (int nt = 0; nt < 4; nt++)
#pragma unroll
            for (int j = 0; j < 4; j++) acc[mt][nt][j] = 0.f;

    TOB_CPA(0, 0);
    if (iters > 1) TOB_CPA(1, 1);

    int cur = 0;
    for (int i = 0; i < iters; i++) {
        if (i + 2 < iters) { CPA_WAIT1(); } else { CPA_WAIT0(); }
        __syncthreads();
        if (i + 2 < iters) {
            int nb3 = cur + 2; if (nb3 >= 3) nb3 -= 3;
            TOB_CPA(i + 2, nb3);
        }

#pragma unroll
        for (int ks = 0; ks < 4; ks++) {
            int kf = ks*8 + lcol;
            float m0 = SMS(cur, kf), m1 = SMS(cur, kf+4);
            uint32_t Af[2][4];
#pragma unroll
            for (int mt = 0; mt < 2; mt++) {
                int m = wm*32 + mt*16 + lrow;
                Af[mt][0] = tf32u(SE(cur, kf,   m));
                Af[mt][1] = tf32u(SE(cur, kf,   m+8));
                Af[mt][2] = tf32u(SE(cur, kf+4, m));
                Af[mt][3] = tf32u(SE(cur, kf+4, m+8));
            }
#pragma unroll
            for (int nt = 0; nt < 4; nt++) {
                int c = wn*32 + nt*8 + lrow;
                uint32_t b0 = tf32u(SX(cur, kf,   c) * m0);
                uint32_t b1 = tf32u(SX(cur, kf+4, c) * m1);
#pragma unroll
                for (int mt = 0; mt < 2; mt++)
                    mma8(acc[mt][nt], Af[mt], b0, b1);
            }
        }
        cur++; if (cur >= 3) cur -= 3;
    }

#pragma unroll
    for (int mt = 0; mt < 2; mt++) {
#pragma unroll
        for (int nt = 0; nt < 4; nt++) {
            int row0 = wm*32 + mt*16 + lrow;
            int col  = c0 + wn*32 + nt*8 + 2*lcol;
            float* p0 = &spec[((size_t)b*KK + row0    ) * CC + col];
            float* p1 = &spec[((size_t)b*KK + row0 + 8) * CC + col];
            atomicAdd(p0,     acc[mt][nt][0]);
            atomicAdd(p0 + 1, acc[mt][nt][1]);
            atomicAdd(p1,     acc[mt][nt][2]);
            atomicAdd(p1 + 1, acc[mt][nt][3]);
        }
    }
}

// =====================================================================
// generic single-pass tf32 mma GEMM, 3-stage cp.async ring, 32-deep chunks.
// smem per stage: A raw [128][36], B raw [32][72]
// =====================================================================
#define GEMM_STAGE (128*36 + 32*72)                 // 6912 floats
#define GEMM_SMEM_FLOATS (3*GEMM_STAGE)             // 20736 floats = 82944 B

__global__ void __launch_bounds__(256,2) k_gemm_mma(
    const float* __restrict__ A, const int* __restrict__ gidx, long long aBatch,
    const float* __restrict__ W0, const float* __restrict__ W1,
    const float* __restrict__ W2, long long wBatch,
    const float* __restrict__ bias0, const float* __restrict__ bias1,
    const float* __restrict__ bias2,
    float* __restrict__ out0, float* __restrict__ out1, float* __restrict__ out2,
    long long oBatch, int Kd, int nW)
{
    extern __shared__ float sm[];
#define SA(bf,r,k) sm[(bf)*GEMM_STAGE + (r)*36 + (k)]
#define SB(bf,r,c) sm[(bf)*GEMM_STAGE + 128*36 + (r)*72 + (c)]

    int z   = blockIdx.z;
    int b   = z / nW;
    int sel = z - b * nW;
    int r0  = blockIdx.x * 128;
    int c0  = blockIdx.y * 64;

    const float* W    = (sel == 0) ? W0    : (sel == 1) ? W1    : W2;
    const float* bias = (sel == 0) ? bias0 : (sel == 1) ? bias1 : bias2;
    float*       out  = (sel == 0) ? out0  : (sel == 1) ? out1  : out2;

    int tid  = threadIdx.x;
    int wid  = tid >> 5, lane = tid & 31;
    int wm   = wid & 3;
    int wn   = wid >> 2;
    int lrow = lane >> 2;
    int lcol = lane & 3;

    const float* Ab = A + (size_t)b * aBatch;
    const float* Wb = W + (size_t)b * wBatch;
    float*       Ob = out + (size_t)b * oBatch;

    int iters = Kd >> 5;

    int ar[4], ak[4], ga[4];
#pragma unroll
    for (int j = 0; j < 4; j++) {
        int f = tid + j*256;
        ar[j] = f >> 3; ak[j] = (f & 7) * 4;
        ga[j] = gidx ? gidx[b*MM + r0 + ar[j]] : (r0 + ar[j]);
    }
    int br[2], bc[2];
#pragma unroll
    for (int j = 0; j < 2; j++) { int f = tid + j*256; br[j] = f >> 4; bc[j] = (f & 15) * 4; }

#define G_CPA(it, bf) {                                                        \
        int kc = (it) << 5;                                                    \
        _Pragma("unroll")                                                      \
        for (int j = 0; j < 4; j++)                                            \
            cpa16(&SA(bf, ar[j], ak[j]), Ab + (size_t)ga[j] * Kd + kc + ak[j]); \
        _Pragma("unroll")                                                      \
        for (int j = 0; j < 2; j++)                                            \
            cpa16(&SB(bf, br[j], bc[j]), Wb + (size_t)(kc + br[j]) * CC + c0 + bc[j]); \
        CPA_COMMIT();                                                          \
    }

    float acc[2][4][4];
#pragma unroll
    for (int mt = 0; mt < 2; mt++)
#pragma unroll
        for (int nt = 0; nt < 4; nt++)
#pragma unroll
            for (int j = 0; j < 4; j++) acc[mt][nt][j] = 0.f;

    G_CPA(0, 0);
    if (iters > 1) G_CPA(1, 1);

    int cur = 0;
    for (int i = 0; i < iters; i++) {
        if (i + 2 < iters) { CPA_WAIT1(); } else { CPA_WAIT0(); }
        __syncthreads();
        if (i + 2 < iters) {
            int nb3 = cur + 2; if (nb3 >= 3) nb3 -= 3;
            G_CPA(i + 2, nb3);
        }

#pragma unroll
        for (int ks = 0; ks < 4; ks++) {
            int kf = ks*8 + lcol;
            uint32_t Af[2][4];
#pragma unroll
            for (int mt = 0; mt < 2; mt++) {
                int m = wm*32 + mt*16 + lrow;
                Af[mt][0] = tf32u(SA(cur, m,   kf));
                Af[mt][1] = tf32u(SA(cur, m+8, kf));
                Af[mt][2] = tf32u(SA(cur, m,   kf+4));
                Af[mt][3] = tf32u(SA(cur, m+8, kf+4));
            }
#pragma unroll
            for (int nt = 0; nt < 4; nt++) {
                int c = wn*32 + nt*8 + lrow;
                uint32_t b0 = tf32u(SB(cur, kf,   c));
                uint32_t b1 = tf32u(SB(cur, kf+4, c));
#pragma unroll
                for (int mt = 0; mt < 2; mt++)
                    mma8(acc[mt][nt], Af[mt], b0, b1);
            }
        }
        cur++; if (cur >= 3) cur -= 3;
    }

#pragma unroll
    for (int mt = 0; mt < 2; mt++) {
#pragma unroll
        for (int nt = 0; nt < 4; nt++) {
            int row0 = r0 + wm*32 + mt*16 + lrow;
            int col  = c0 + wn*32 + nt*8 + 2*lcol;
            float b0v = bias ? bias[col]     : 0.f;
            float b1v = bias ? bias[col + 1] : 0.f;
            float2 v0 = {acc[mt][nt][0] + b0v, acc[mt][nt][1] + b1v};
            float2 v1 = {acc[mt][nt][2] + b0v, acc[mt][nt][3] + b1v};
            *reinterpret_cast<float2*>(&Ob[(size_t)row0       * CC + col]) = v0;
            *reinterpret_cast<float2*>(&Ob[(size_t)(row0 + 8) * CC + col]) = v1;
        }
    }
}

// ---------------- spectral coefficient multiply (+ optional out_w fold) ----------------
__global__ void k_coef(const float* __restrict__ evals, const float* __restrict__ tvec,
                       const float* __restrict__ specin, float* __restrict__ specout,
                       const float* __restrict__ outw)
{
    int bk = blockIdx.x;
    int b = bk >> 7, k = bk & 127;
    int c = threadIdx.x;
    float t = fmaxf(tvec[c], 1e-8f);
    float w = outw ? fmaxf(outw[c], 1e-8f) : 1.f;
    specout[(size_t)bk*CC + c] = expf(-evals[b*KK + k] * t) * specin[(size_t)bk*CC + c] * w;
}

// ---------------- GroupNorm stats ----------------
__global__ void k_gnstats()
{
    int b = blockIdx.x >> 5, g = blockIdx.x & 31;
    int tid = threadIdx.x;
    float s = 0.f, s2 = 0.f;
    for (int e = tid; e < MM*8; e += 256) {
        int m = e >> 3, j = e & 7;
        float v = g_xfar[((size_t)(b*MM + m)) * CC + (g << 3) + j];
        s += v; s2 += v * v;
    }
    __shared__ float rs[256], rq[256];
    rs[tid] = s; rq[tid] = s2;
    __syncthreads();
    for (int o = 128; o > 0; o >>= 1) {
        if (tid < o) { rs[tid] += rs[tid+o]; rq[tid] += rq[tid+o]; }
        __syncthreads();
    }
    if (tid == 0) {
        float mean = rs[0] * (1.f/8192.f);
        float var  = rq[0] * (1.f/8192.f) - mean*mean;
        g_gnm[blockIdx.x] = mean;
        g_gnr[blockIdx.x] = rsqrtf(var + 1e-6f);
    }
}

// ---------------- GroupNorm apply (in place) ----------------
__global__ void k_gnapply(const float* __restrict__ gn_w, const float* __restrict__ gn_b)
{
    int i = blockIdx.x * blockDim.x + threadIdx.x;
    int base = i * 4;
    int c  = base & 255;
    int bm = base >> 8;
    int b  = bm >> 10;
    int g  = c >> 3;
    float mean = g_gnm[b*GG + g];
    float r    = g_gnr[b*GG + g];
    float4 v = *reinterpret_cast<float4*>(&g_xfar[base]);
    v.x = (v.x - mean) * r * gn_w[c+0] + gn_b[c+0];
    v.y = (v.y - mean) * r * gn_w[c+1] + gn_b[c+1];
    v.z = (v.z - mean) * r * gn_w[c+2] + gn_b[c+2];
    v.w = (v.w - mean) * r * gn_w[c+3] + gn_b[c+3];
    *reinterpret_cast<float4*>(&g_xfar[base]) = v;
}

// =====================================================================
// flash attention with single-pass tf32 mma, raw-fp32 smem.
// (unchanged — protected win)
// =====================================================================
#define ATT_KP 69
#define ATT_VP 40
#define ATT_PP 68
#define ATT_QP 36
#define ATT_SMEM_FLOATS (32*ATT_KP + 64*ATT_VP + 64*ATT_PP + 256)   // 9376 floats

__global__ void __launch_bounds__(256,2) k_attn_mma()
{
    extern __shared__ float sm[];
    float* sK  = sm;                        // [32][69] raw, transposed [d][key]
    float* sV  = sK + 32*ATT_KP;            // [64][40] raw
    float* sP  = sV + 64*ATT_VP;            // [64][68] raw (Q staging [64][36])
    float* sRm = sP + 64*ATT_PP;            // [2][64]
    float* sRl = sRm + 128;                 // [2][64]

    int b = blockIdx.z, h = blockIdx.y, q0 = blockIdx.x * 64;
    int tid = threadIdx.x;
    int wid = tid >> 5, lane = tid & 31;
    int wm = wid & 3, wn = wid >> 2;
    int lrow = lane >> 2, lcol = lane & 3;
    const float scale = 0.17677669529663687f;   // 1/sqrt(32)
    const float L2E = 1.4426950408889634f;

#pragma unroll
    for (int v = tid; v < 512; v += 256) {
        int r = v >> 3, d0 = (v & 7) * 4;
        float4 qv = *reinterpret_cast<const float4*>(
            &g_q[((size_t)(b*MM) + q0 + r) * CC + h*DD + d0]);
        qv.x *= scale; qv.y *= scale; qv.z *= scale; qv.w *= scale;
        *reinterpret_cast<float4*>(&sP[r*ATT_QP + d0]) = qv;
    }
    __syncthreads();

    uint32_t Aq[4][4];
    {
        int m = 16*wm + lrow;
#pragma unroll
        for (int ks = 0; ks < 4; ks++) {
            int kf = ks*8 + lcol;
            Aq[ks][0] = tf32u(sP[m*ATT_QP + kf]);
            Aq[ks][1] = tf32u(sP[(m+8)*ATT_QP + kf]);
            Aq[ks][2] = tf32u(sP[m*ATT_QP + kf + 4]);
            Aq[ks][3] = tf32u(sP[(m+8)*ATT_QP + kf + 4]);
        }
    }

    float oacc[2][4];
#pragma unroll
    for (int nt = 0; nt < 2; nt++)
#pragma unroll
        for (int j = 0; j < 4; j++) oacc[nt][j] = 0.f;
    float mrun0 = -1e30f, mrun1 = -1e30f, lrun0 = 0.f, lrun1 = 0.f;
    int rbase = 16*wm + lrow;

    for (int kt = 0; kt < 16; kt++) {
        __syncthreads();
#pragma unroll
        for (int v = tid; v < 512; v += 256) {
            int r = v >> 3, d0 = (v & 7) * 4;
            size_t gi = ((size_t)b*MM + kt*64 + r) * CC + h*DD + d0;
            float4 kv = *reinterpret_cast<const float4*>(&g_kmat[gi]);
            sK[(d0+0)*ATT_KP + r] = kv.x;
            sK[(d0+1)*ATT_KP + r] = kv.y;
            sK[(d0+2)*ATT_KP + r] = kv.z;
            sK[(d0+3)*ATT_KP + r] = kv.w;
            float4 vv = *reinterpret_cast<const float4*>(&g_v[gi]);
            *reinterpret_cast<float4*>(&sV[r*ATT_VP + d0]) = vv;
        }
        __syncthreads();

        float s[4][4];
#pragma unroll
        for (int nt = 0; nt < 4; nt++)
#pragma unroll
            for (int j = 0; j < 4; j++) s[nt][j] = 0.f;
#pragma unroll
        for (int ks = 0; ks < 4; ks++) {
            int kf = ks*8 + lcol;
#pragma unroll
            for (int nt = 0; nt < 4; nt++) {
                int key = wn*32 + nt*8 + lrow;
                uint32_t b0 = tf32u(sK[kf*ATT_KP + key]);
                uint32_t b1 = tf32u(sK[(kf+4)*ATT_KP + key]);
                mma8(s[nt], Aq[ks], b0, b1);
            }
        }

        float t0 = -1e30f, t1 = -1e30f;
#pragma unroll
        for (int nt = 0; nt < 4; nt++) {
            t0 = fmaxf(t0, fmaxf(s[nt][0], s[nt][1]));
            t1 = fmaxf(t1, fmaxf(s[nt][2], s[nt][3]));
        }
        t0 = fmaxf(t0, __shfl_xor_sync(0xffffffff, t0, 1));
        t0 = fmaxf(t0, __shfl_xor_sync(0xffffffff, t0, 2));
        t1 = fmaxf(t1, __shfl_xor_sync(0xffffffff, t1, 1));
        t1 = fmaxf(t1, __shfl_xor_sync(0xffffffff, t1, 2));
        if (lcol == 0) {
            sRm[wn*64 + rbase]     = t0;
            sRm[wn*64 + rbase + 8] = t1;
        }
        __syncthreads();
        float mnew0 = fmaxf(mrun0, fmaxf(sRm[rbase],     sRm[64 + rbase]));
        float mnew1 = fmaxf(mrun1, fmaxf(sRm[rbase + 8], sRm[64 + rbase + 8]));

        float ls0 = 0.f, ls1 = 0.f;
#pragma unroll
        for (int nt = 0; nt < 4; nt++) {
            float p0 = exp2f((s[nt][0] - mnew0) * L2E);
            float p1 = exp2f((s[nt][1] - mnew0) * L2E);
            float p2 = exp2f((s[nt][2] - mnew1) * L2E);
            float p3 = exp2f((s[nt][3] - mnew1) * L2E);
            ls0 += p0 + p1;
            ls1 += p2 + p3;
            int col = wn*32 + nt*8 + 2*lcol;
            float2 w0 = {p0, p1}, w1 = {p2, p3};
            *reinterpret_cast<float2*>(&sP[rbase*ATT_PP + col])     = w0;
            *reinterpret_cast<float2*>(&sP[(rbase+8)*ATT_PP + col]) = w1;
        }
        ls0 += __shfl_xor_sync(0xffffffff, ls0, 1);
        ls0 += __shfl_xor_sync(0xffffffff, ls0, 2);
        ls1 += __shfl_xor_sync(0xffffffff, ls1, 1);
        ls1 += __shfl_xor_sync(0xffffffff, ls1, 2);
        if (lcol == 0) {
            sRl[wn*64 + rbase]     = ls0;
            sRl[wn*64 + rbase + 8] = ls1;
        }
        __syncthreads();
        float lt0 = sRl[rbase]     + sRl[64 + rbase];
        float lt1 = sRl[rbase + 8] + sRl[64 + rbase + 8];
        float c0 = exp2f((mrun0 - mnew0) * L2E);
        float c1 = exp2f((mrun1 - mnew1) * L2E);
        lrun0 = lrun0 * c0 + lt0;
        lrun1 = lrun1 * c1 + lt1;
        mrun0 = mnew0; mrun1 = mnew1;
#pragma unroll
        for (int nt = 0; nt < 2; nt++) {
            oacc[nt][0] *= c0; oacc[nt][1] *= c0;
            oacc[nt][2] *= c1; oacc[nt][3] *= c1;
        }

#pragma unroll
        for (int ks = 0; ks < 8; ks++) {
            int kf = ks*8 + lcol;
            uint32_t Ap[4];
            Ap[0] = tf32u(sP[rbase*ATT_PP + kf]);
            Ap[1] = tf32u(sP[(rbase+8)*ATT_PP + kf]);
            Ap[2] = tf32u(sP[rbase*ATT_PP + kf + 4]);
            Ap[3] = tf32u(sP[(rbase+8)*ATT_PP + kf + 4]);
#pragma unroll
            for (int nt = 0; nt < 2; nt++) {
                int d = wn*16 + nt*8 + lrow;
                uint32_t b0 = tf32u(sV[kf*ATT_VP + d]);
                uint32_t b1 = tf32u(sV[(kf+4)*ATT_VP + d]);
                mma8(oacc[nt], Ap, b0, b1);
            }
        }
    }

    float i0 = 1.f / lrun0, i1 = 1.f / lrun1;
#pragma unroll
    for (int nt = 0; nt < 2; nt++) {
        int col = h*DD + wn*16 + nt*8 + 2*lcol;
        size_t o0 = ((size_t)(b*MM) + q0 + rbase) * CC + col;
        size_t o1 = ((size_t)(b*MM) + q0 + rbase + 8) * CC + col;
        float2 w0 = {oacc[nt][0]*i0, oacc[nt][1]*i0};
        float2 w1 = {oacc[nt][2]*i1, oacc[nt][3]*i1};
        *reinterpret_cast<float2*>(&g_ao[o0]) = w0;
        *reinterpret_cast<float2*>(&g_ao[o1]) = w1;
    }
}

// ---------------- launch ----------------
extern "C" void kernel_launch(void* const* d_in, const int* in_sizes, int n_in,
                              void* d_out, int out_size)
{
    const float* x       = (const float*)d_in[0];
    const float* mass    = (const float*)d_in[1];
    const float* evals   = (const float*)d_in[2];
    const float* evecs   = (const float*)d_in[3];
    const int*   far_idx = (const int*)  d_in[4];
    const float* t_in    = (const float*)d_in[5];
    const float* t_out   = (const float*)d_in[6];
    const float* gn_w    = (const float*)d_in[7];
    const float* gn_b    = (const float*)d_in[8];
    const float* Wq      = (const float*)d_in[9];
    const float* bq      = (const float*)d_in[10];
    const float* Wk      = (const float*)d_in[11];
    const float* bk      = (const float*)d_in[12];
    const float* Wv      = (const float*)d_in[13];
    const float* bv      = (const float*)d_in[14];
    const float* Wo      = (const float*)d_in[15];
    const float* bo      = (const float*)d_in[16];
    const float* out_w   = (const float*)d_in[17];
    float* out = (float*)d_out;

    static int s_attr_done = 0;
    const int TOB_SMEM  = TOB_SMEM_FLOATS  * 4;
    const int GEMM_SMEM = GEMM_SMEM_FLOATS * 4;
    const int ATT_SMEM  = ATT_SMEM_FLOATS  * 4;
    if (!s_attr_done) {
        cudaFuncSetAttribute(k_tobasis_mma, cudaFuncAttributeMaxDynamicSharedMemorySize, TOB_SMEM);
        cudaFuncSetAttribute(k_gemm_mma,    cudaFuncAttributeMaxDynamicSharedMemorySize, GEMM_SMEM);
        cudaFuncSetAttribute(k_attn_mma,    cudaFuncAttributeMaxDynamicSharedMemorySize, ATT_SMEM);
        s_attr_done = 1;
    }

    float *p_spec1, *p_spec1m, *p_spec2, *p_spec2m, *p_xfar, *p_q, *p_k, *p_v, *p_ao, *p_proj;
    cudaGetSymbolAddress((void**)&p_spec1,  g_spec1);
    cudaGetSymbolAddress((void**)&p_spec1m, g_spec1m);
    cudaGetSymbolAddress((void**)&p_spec2,  g_spec2);
    cudaGetSymbolAddress((void**)&p_spec2m, g_spec2m);
    cudaGetSymbolAddress((void**)&p_xfar,   g_xfar);
    cudaGetSymbolAddress((void**)&p_q,      g_q);
    cudaGetSymbolAddress((void**)&p_k,      g_kmat);
    cudaGetSymbolAddress((void**)&p_v,      g_v);
    cudaGetSymbolAddress((void**)&p_ao,     g_ao);
    cudaGetSymbolAddress((void**)&p_proj,   g_proj);

    const long long AKC = (long long)KK * CC;
    const long long AMC = (long long)MM * CC;
    const long long ANK = (long long)NN * KK;
    const long long ANC = (long long)NN * CC;

    k_zero<<<512, 256>>>();

    // to_basis 1: full N, split-K over 32 chunks of 1024
    k_tobasis_mma<<<dim3(32, 4, BB), 256, TOB_SMEM>>>(x, mass, evecs, nullptr, p_spec1, 1024, NN);
    k_coef<<<BB*KK, CC>>>(evals, t_in, p_spec1, p_spec1m, nullptr);

    // from_basis 1: only the M gathered rows
    k_gemm_mma<<<dim3(MM/128, 4, BB), 256, GEMM_SMEM>>>(
        evecs, far_idx, ANK,
        p_spec1m, nullptr, nullptr, AKC,
        nullptr, nullptr, nullptr,
        p_xfar, nullptr, nullptr, AMC, KK, 1);

    // GroupNorm
    k_gnstats<<<BB*GG, 256>>>();
    k_gnapply<<<(BB*MM*CC/4)/256, 256>>>(gn_w, gn_b);

    // QKV projections fused (nW=3)
    k_gemm_mma<<<dim3(MM/128, 4, BB*3), 256, GEMM_SMEM>>>(
        p_xfar, nullptr, AMC,
        Wq, Wk, Wv, 0,
        bq, bk, bv,
        p_q, p_k, p_v, AMC, CC, 3);

    // attention (tensor-core flash, single-pass tf32)
    k_attn_mma<<<dim3(MM/64, HH, BB), 256, ATT_SMEM>>>();

    // output projection
    k_gemm_mma<<<dim3(MM/128, 4, BB), 256, GEMM_SMEM>>>(
        p_ao, nullptr, AMC,
        Wo, nullptr, nullptr, 0,
        bo, nullptr, nullptr,
        p_proj, nullptr, nullptr, AMC, CC, 1);

    // to_basis 2: only the M scattered rows
    k_tobasis_mma<<<dim3(8, 4, BB), 256, TOB_SMEM>>>(p_proj, mass, evecs, far_idx, p_spec2, 128, MM);
    k_coef<<<BB*KK, CC>>>(evals, t_out, p_spec2, p_spec2m, out_w);

    // from_basis 2: full N output (out_w folded into spec2m)
    k_gemm_mma<<<dim3(NN/128, 4, BB), 256, GEMM_SMEM>>>(
        evecs, nullptr, ANK,
        p_spec2m, nullptr, nullptr, AKC,
        nullptr, nullptr, nullptr,
        out, nullptr, nullptr, ANC, KK, 1);
}